// round 5
// baseline (speedup 1.0000x reference)
#include <cuda_runtime.h>
#include <cstdint>
#include <cstddef>

#define HSZ 1024
#define BSZ 16
#define TSTEPS 257
#define SENC 512
#define ESZ 512
#define MROWS (BSZ*TSTEPS)
typedef unsigned long long ull;

// ------------- device scratch (statics; no allocations) -------------
__device__ float g_X0[(size_t)MROWS * 4096];      // [t*16+b][gate_row] row-major
__device__ float g_hs[(size_t)MROWS * HSZ];       // [b*257+t][j]
__device__ float g_ctx[(size_t)MROWS * HSZ];
__device__ float g_att[(size_t)MROWS * SENC];
__device__ float g_hidden[(size_t)MROWS * HSZ];
__device__ float g_logits[(size_t)MROWS * HSZ];   // V==1024
__device__ float g_hp[3][2][BSZ * HSZ];           // ping-pong hidden per layer
__device__ float g_c[3][BSZ * HSZ];               // cell state per layer
__device__ float g_nll[MROWS];
__device__ int   g_tok[MROWS];                    // dec_in, index t*16+b
__device__ int   g_tgt[MROWS];                    // dec_out, index b*257+t

#define FMA2(a,x,y) asm("fma.rn.f32x2 %0, %1, %2, %0;" : "+l"(a) : "l"(x), "l"(y))
__device__ __forceinline__ float sigm(float x){ return 1.f/(1.f+expf(-x)); }

// ------------- init -------------
__global__ void k_init(const int* __restrict__ tokens){
  int i = blockIdx.x*blockDim.x + threadIdx.x;
  if (i < 3*2*BSZ*HSZ) ((float*)g_hp)[i] = 0.f;
  if (i < 3*BSZ*HSZ)   ((float*)g_c)[i]  = 0.f;
  if (i < MROWS){
    int t = i / BSZ, b = i % BSZ;
    g_tok[i] = (t == 0) ? 1 : tokens[b*256 + (t-1)];
    int b2 = i / TSTEPS, t2 = i % TSTEPS;
    g_tgt[i] = (t2 < 256) ? tokens[b2*256 + t2] : 2;
  }
}

// ------------- NT GEMM: C = A(MxK) * B(NxK)^T, options -------------
__global__ void __launch_bounds__(256) k_gemm_nt(
    const float* __restrict__ A, int lda, long long sA,
    const float* __restrict__ A2, int lda2, int ksplit, int gather,
    const float* __restrict__ B, int ldb, long long sB,
    float* __restrict__ C, int ldc, long long sC,
    int M, int N, int K, const float* __restrict__ bias, int act)
{
  __shared__ float As[16][68];
  __shared__ float Bs[16][68];
  int z = blockIdx.z;
  const float* Ab = A + (size_t)z * sA;
  const float* Bb = B + (size_t)z * sB;
  float* Cb = C + (size_t)z * sC;
  int m0 = blockIdx.y*64, n0 = blockIdx.x*64;
  int tid = threadIdx.x;
  int tx = tid & 15, ty = tid >> 4;
  float acc[4][4];
#pragma unroll
  for (int i=0;i<4;i++)
#pragma unroll
    for (int j=0;j<4;j++) acc[i][j] = 0.f;

  int r = tid >> 2, c4 = (tid & 3) * 4;

  for (int k0 = 0; k0 < K; k0 += 16){
    float4 va = make_float4(0.f,0.f,0.f,0.f);
    int m = m0 + r;
    if (m < M){
      int kg = k0 + c4;
      int row = gather ? g_tok[m] : m;
      const float* src;
      if (A2 && kg >= ksplit) src = A2 + (size_t)row*lda2 + (kg - ksplit);
      else                    src = Ab + (size_t)row*lda + kg;
      va = *reinterpret_cast<const float4*>(src);
    }
    As[c4+0][r]=va.x; As[c4+1][r]=va.y; As[c4+2][r]=va.z; As[c4+3][r]=va.w;
    float4 vb = *reinterpret_cast<const float4*>(Bb + (size_t)(n0+r)*ldb + k0 + c4);
    Bs[c4+0][r]=vb.x; Bs[c4+1][r]=vb.y; Bs[c4+2][r]=vb.z; Bs[c4+3][r]=vb.w;
    __syncthreads();
#pragma unroll
    for (int kk=0;kk<16;kk++){
      float4 a = *reinterpret_cast<const float4*>(&As[kk][ty*4]);
      float4 b = *reinterpret_cast<const float4*>(&Bs[kk][tx*4]);
      acc[0][0]+=a.x*b.x; acc[0][1]+=a.x*b.y; acc[0][2]+=a.x*b.z; acc[0][3]+=a.x*b.w;
      acc[1][0]+=a.y*b.x; acc[1][1]+=a.y*b.y; acc[1][2]+=a.y*b.z; acc[1][3]+=a.y*b.w;
      acc[2][0]+=a.z*b.x; acc[2][1]+=a.z*b.y; acc[2][2]+=a.z*b.z; acc[2][3]+=a.z*b.w;
      acc[3][0]+=a.w*b.x; acc[3][1]+=a.w*b.y; acc[3][2]+=a.w*b.z; acc[3][3]+=a.w*b.w;
    }
    __syncthreads();
  }
#pragma unroll
  for (int i=0;i<4;i++){
    int m = m0 + ty*4 + i;
    if (m < M){
#pragma unroll
      for (int j=0;j<4;j++){
        int n = n0 + tx*4 + j;
        float v = acc[i][j];
        if (bias) v += bias[n];
        if (act)  v = tanhf(v);
        Cb[(size_t)m*ldc + n] = v;
      }
    }
  }
}

// ------------- NN GEMM: C = A(MxK) * B(KxN) -------------
__global__ void __launch_bounds__(256) k_gemm_nn(
    const float* __restrict__ A, int lda, long long sA,
    const float* __restrict__ B, int ldb, long long sB,
    float* __restrict__ C, int ldc, long long sC,
    int M, int N, int K)
{
  __shared__ float As[16][68];
  __shared__ float Bs[16][68];
  int z = blockIdx.z;
  const float* Ab = A + (size_t)z*sA;
  const float* Bb = B + (size_t)z*sB;
  float* Cb = C + (size_t)z*sC;
  int m0 = blockIdx.y*64, n0 = blockIdx.x*64;
  int tid = threadIdx.x;
  int tx = tid & 15, ty = tid >> 4;
  float acc[4][4];
#pragma unroll
  for (int i=0;i<4;i++)
#pragma unroll
    for (int j=0;j<4;j++) acc[i][j]=0.f;

  int r = tid >> 2, c4 = (tid & 3)*4;
  int kr = tid >> 4, nc4 = (tid & 15)*4;

  for (int k0=0;k0<K;k0+=16){
    float4 va = make_float4(0.f,0.f,0.f,0.f);
    int m = m0 + r;
    if (m < M) va = *reinterpret_cast<const float4*>(Ab + (size_t)m*lda + k0 + c4);
    As[c4+0][r]=va.x; As[c4+1][r]=va.y; As[c4+2][r]=va.z; As[c4+3][r]=va.w;
    float4 vb = *reinterpret_cast<const float4*>(Bb + (size_t)(k0+kr)*ldb + n0 + nc4);
    Bs[kr][nc4+0]=vb.x; Bs[kr][nc4+1]=vb.y; Bs[kr][nc4+2]=vb.z; Bs[kr][nc4+3]=vb.w;
    __syncthreads();
#pragma unroll
    for (int kk=0;kk<16;kk++){
      float4 a = *reinterpret_cast<const float4*>(&As[kk][ty*4]);
      float4 b = *reinterpret_cast<const float4*>(&Bs[kk][tx*4]);
      acc[0][0]+=a.x*b.x; acc[0][1]+=a.x*b.y; acc[0][2]+=a.x*b.z; acc[0][3]+=a.x*b.w;
      acc[1][0]+=a.y*b.x; acc[1][1]+=a.y*b.y; acc[1][2]+=a.y*b.z; acc[1][3]+=a.y*b.w;
      acc[2][0]+=a.z*b.x; acc[2][1]+=a.z*b.y; acc[2][2]+=a.z*b.z; acc[2][3]+=a.z*b.w;
      acc[3][0]+=a.w*b.x; acc[3][1]+=a.w*b.y; acc[3][2]+=a.w*b.z; acc[3][3]+=a.w*b.w;
    }
    __syncthreads();
  }
#pragma unroll
  for (int i=0;i<4;i++){
    int m = m0 + ty*4 + i;
    if (m < M){
#pragma unroll
      for (int j=0;j<4;j++) Cb[(size_t)m*ldc + (n0 + tx*4 + j)] = acc[i][j];
    }
  }
}

// ------------- one LSTM (t, layer) step: 256 blocks x 512 threads -------------
// warp = one gate row (r) of one unit (j), all 16 batches.
__global__ void __launch_bounds__(512,1) k_step(
    const float* __restrict__ Wih,   // null for layer 0 (x-part precomputed in g_X0)
    const float* __restrict__ Whh,
    const float* __restrict__ bi, const float* __restrict__ bh,
    const float* __restrict__ hin,   // lower-layer h (this step); null for layer 0
    const float* __restrict__ hprev, // this layer's h from previous step
    float* __restrict__ hout,
    float* __restrict__ cstate,      // [16*1024] b-major
    const float* __restrict__ x0,    // g_X0 + t*16*4096 for layer 0, else null
    float* __restrict__ hs_out,      // g_hs for layer 2, else null
    int t)
{
  __shared__ float sbuf[BSZ*512];
  __shared__ float sg[4][4][16];
  int tid = threadIdx.x, lane = tid & 31, wid = tid >> 5;
  int junit = wid >> 2, r = wid & 3;
  int j = blockIdx.x*4 + junit;
  int row = (r << 10) + j;

  ull acc[16];
#pragma unroll
  for (int b=0;b<16;b++) acc[b] = 0ull;

  const float* Wq[2]; const float* Sq[2]; int nq = 0;
  if (Wih){ Wq[nq] = Wih; Sq[nq] = hin; nq++; }
  Wq[nq] = Whh; Sq[nq] = hprev; nq++;

  for (int q=0;q<nq;q++){
    const float* W = Wq[q];
    const float* S = Sq[q];
#pragma unroll
    for (int half=0;half<2;half++){
      int kbase = half*512;
      __syncthreads();
#pragma unroll
      for (int i=0;i<4;i++){
        int idx = tid + i*512;
        int b = idx >> 7, c = idx & 127;
        ((float4*)sbuf)[idx] = *((const float4*)(S + (b<<10) + kbase) + c);
      }
      __syncthreads();
      ull wv[8];
#pragma unroll
      for (int m=0;m<8;m++)
        wv[m] = *(const ull*)(W + (size_t)row*1024 + kbase + ((lane + (m<<5))<<1));
#pragma unroll
      for (int b=0;b<16;b++){
#pragma unroll
        for (int m=0;m<8;m++){
          ull hv = *(const ull*)(sbuf + (b<<9) + ((lane + (m<<5))<<1));
          FMA2(acc[b], wv[m], hv);
        }
      }
    }
  }

  // reduce 32 lanes; lane b keeps gate value of batch b
  float gv = 0.f;
#pragma unroll
  for (int b=0;b<16;b++){
    ull v = acc[b];
    float s = __uint_as_float((unsigned)v) + __uint_as_float((unsigned)(v>>32));
    s += __shfl_xor_sync(0xffffffffu, s, 16);
    s += __shfl_xor_sync(0xffffffffu, s, 8);
    s += __shfl_xor_sync(0xffffffffu, s, 4);
    s += __shfl_xor_sync(0xffffffffu, s, 2);
    s += __shfl_xor_sync(0xffffffffu, s, 1);
    if (lane == b) gv = s;
  }
  if (lane < 16){
    gv += bi[row] + bh[row];
    if (x0) gv += x0[(size_t)lane*4096 + row];
    sg[junit][r][lane] = gv;
  }
  __syncthreads();

  if (r == 0 && lane < 16){
    int b = lane;
    float iv = sigm(sg[junit][0][b]);
    float fv = sigm(sg[junit][1][b]);
    float gg = tanhf(sg[junit][2][b]);
    float ov = sigm(sg[junit][3][b]);
    int ci = (b<<10) + j;
    float c = fv*cstate[ci] + iv*gg;
    cstate[ci] = c;
    float h = ov * tanhf(c);
    hout[ci] = h;
    if (hs_out) hs_out[((size_t)b*TSTEPS + t)*HSZ + j] = h;
  }
}

// ------------- softmax over S=512 -------------
__global__ void k_softmax(){
  int m = blockIdx.x;
  float* row = g_att + (size_t)m * SENC;
  int tid = threadIdx.x;            // 128
  __shared__ float sm[4];
  float v[4];
#pragma unroll
  for (int i=0;i<4;i++) v[i] = row[tid + 128*i];
  float mx = fmaxf(fmaxf(v[0],v[1]), fmaxf(v[2],v[3]));
#pragma unroll
  for (int o=16;o>0;o>>=1) mx = fmaxf(mx, __shfl_xor_sync(0xffffffffu, mx, o));
  if ((tid & 31) == 0) sm[tid>>5] = mx;
  __syncthreads();
  mx = fmaxf(fmaxf(sm[0],sm[1]), fmaxf(sm[2],sm[3]));
  float s = 0.f;
#pragma unroll
  for (int i=0;i<4;i++){ v[i] = expf(v[i]-mx); s += v[i]; }
#pragma unroll
  for (int o=16;o>0;o>>=1) s += __shfl_xor_sync(0xffffffffu, s, o);
  __syncthreads();
  if ((tid & 31) == 0) sm[tid>>5] = s;
  __syncthreads();
  s = sm[0]+sm[1]+sm[2]+sm[3];
  float inv = 1.f / s;
#pragma unroll
  for (int i=0;i<4;i++) row[tid + 128*i] = v[i]*inv;
}

// ------------- NLL over V=1024 -------------
__global__ void k_nll(){
  int m = blockIdx.x;
  const float* row = g_logits + (size_t)m * 1024;
  int tid = threadIdx.x;            // 256
  __shared__ float sm[8];
  float v[4];
#pragma unroll
  for (int i=0;i<4;i++) v[i] = row[tid + 256*i];
  float mx = fmaxf(fmaxf(v[0],v[1]), fmaxf(v[2],v[3]));
#pragma unroll
  for (int o=16;o>0;o>>=1) mx = fmaxf(mx, __shfl_xor_sync(0xffffffffu, mx, o));
  if ((tid & 31) == 0) sm[tid>>5] = mx;
  __syncthreads();
  mx = sm[0];
#pragma unroll
  for (int i=1;i<8;i++) mx = fmaxf(mx, sm[i]);
  float s = 0.f;
#pragma unroll
  for (int i=0;i<4;i++) s += expf(v[i]-mx);
#pragma unroll
  for (int o=16;o>0;o>>=1) s += __shfl_xor_sync(0xffffffffu, s, o);
  __syncthreads();
  if ((tid & 31) == 0) sm[tid>>5] = s;
  __syncthreads();
  if (tid == 0){
    float tot = 0.f;
#pragma unroll
    for (int i=0;i<8;i++) tot += sm[i];
    g_nll[m] = (logf(tot) + mx) - row[g_tgt[m]];
  }
}

__global__ void k_final(float* __restrict__ out){
  int tid = threadIdx.x;            // 256
  __shared__ float sm[8];
  float s = 0.f;
  for (int i=tid; i<MROWS; i+=256) s += g_nll[i];
#pragma unroll
  for (int o=16;o>0;o>>=1) s += __shfl_xor_sync(0xffffffffu, s, o);
  if ((tid & 31) == 0) sm[tid>>5] = s;
  __syncthreads();
  if (tid == 0){
    float tot = 0.f;
#pragma unroll
    for (int i=0;i<8;i++) tot += sm[i];
    out[0] = tot / (float)MROWS;
  }
}

// ------------- launcher -------------
extern "C" void kernel_launch(void* const* d_in, const int* in_sizes, int n_in,
                              void* d_out, int out_size)
{
  const int*   tokens = (const int*)  d_in[0];
  const float* enc    = (const float*)d_in[1];
  const float* emb    = (const float*)d_in[2];   // (1024, 512): E = 512 !
  const float* Wih0   = (const float*)d_in[3];   // (4096, 1536): E+ENC2 = 1536 !
  const float* Whh0   = (const float*)d_in[4];
  const float* bi0    = (const float*)d_in[5];
  const float* bh0    = (const float*)d_in[6];
  const float* Wih1   = (const float*)d_in[7];
  const float* Whh1   = (const float*)d_in[8];
  const float* bi1    = (const float*)d_in[9];
  const float* bh1    = (const float*)d_in[10];
  const float* Wih2   = (const float*)d_in[11];
  const float* Whh2   = (const float*)d_in[12];
  const float* bi2    = (const float*)d_in[13];
  const float* bh2    = (const float*)d_in[14];
  const float* W1     = (const float*)d_in[15];
  const float* b1     = (const float*)d_in[16];
  const float* W2     = (const float*)d_in[17];
  const float* b2     = (const float*)d_in[18];
  float* out = (float*)d_out;

  void *pX0,*pHS,*pCTX,*pATT,*pHID,*pLOG,*pHP,*pC;
  cudaGetSymbolAddress(&pX0,  g_X0);
  cudaGetSymbolAddress(&pHS,  g_hs);
  cudaGetSymbolAddress(&pCTX, g_ctx);
  cudaGetSymbolAddress(&pATT, g_att);
  cudaGetSymbolAddress(&pHID, g_hidden);
  cudaGetSymbolAddress(&pLOG, g_logits);
  cudaGetSymbolAddress(&pHP,  g_hp);
  cudaGetSymbolAddress(&pC,   g_c);
  float* X0 = (float*)pX0;
  float* HP = (float*)pHP;   // [3][2][16*1024]
  float* CS = (float*)pC;    // [3][16*1024]

  k_init<<<384,256>>>(tokens);

  // X0[4112, 4096] = gather(emb)[.,512] @ W_ih0[:, :512]^T
  // emb lda = E = 512; W_ih0 ldb = E+ENC2 = 1536; K = 512. Context half of x is zeros.
  k_gemm_nt<<<dim3(64,65,1),256>>>(emb,ESZ,0, nullptr,ESZ,1<<30, 1,
                                   Wih0,1536,0, X0, 4096,0,
                                   MROWS,4096,ESZ, nullptr,0);

  const int HB = BSZ*HSZ;
  for (int t=0; t<TSTEPS; t++){
    int cur = t & 1, prv = cur ^ 1;
    float* h0p = HP + 0*2*HB + prv*HB; float* h0c = HP + 0*2*HB + cur*HB;
    float* h1p = HP + 1*2*HB + prv*HB; float* h1c = HP + 1*2*HB + cur*HB;
    float* h2p = HP + 2*2*HB + prv*HB; float* h2c = HP + 2*2*HB + cur*HB;
    k_step<<<256,512>>>(nullptr, Whh0, bi0, bh0, nullptr, h0p, h0c, CS + 0*HB,
                        X0 + (size_t)t*BSZ*4096, nullptr, t);
    k_step<<<256,512>>>(Wih1, Whh1, bi1, bh1, h0c, h1p, h1c, CS + 1*HB,
                        nullptr, nullptr, t);
    k_step<<<256,512>>>(Wih2, Whh2, bi2, bh2, h1c, h2p, h2c, CS + 2*HB,
                        nullptr, (float*)pHS, t);
  }

  // scores[b]: hs[b] (257x1024) @ enc[b]^T (512x1024)
  k_gemm_nt<<<dim3(8,5,16),256>>>((const float*)pHS,1024,257LL*1024, nullptr,1024,1<<30, 0,
                                  enc,1024,512LL*1024, (float*)pATT,512,257LL*512,
                                  257,512,1024, nullptr,0);

  k_softmax<<<MROWS,128>>>();

  // ctx[b]: attn[b] (257x512) @ enc[b] (512x1024)
  k_gemm_nn<<<dim3(16,5,16),256>>>((const float*)pATT,512,257LL*512,
                                   enc,1024,512LL*1024,
                                   (float*)pCTX,1024,257LL*1024, 257,1024,512);

  // hidden = tanh([hs|ctx] @ W1^T + b1)
  k_gemm_nt<<<dim3(16,65,1),256>>>((const float*)pHS,1024,0, (const float*)pCTX,1024,1024, 0,
                                   W1,2048,0, (float*)pHID,1024,0,
                                   MROWS,1024,2048, b1,1);

  // logits = hidden @ W2^T + b2
  k_gemm_nt<<<dim3(16,65,1),256>>>((const float*)pHID,1024,0, nullptr,1024,1<<30, 0,
                                   W2,1024,0, (float*)pLOG,1024,0,
                                   MROWS,1024,1024, b2,0);

  k_nll<<<MROWS,256>>>();
  k_final<<<1,256>>>(out);
}

// round 6
// speedup vs baseline: 1.9817x; 1.9817x over previous
#include <cuda_runtime.h>
#include <cstdint>
#include <cstddef>

#define HSZ 1024
#define BSZ 16
#define TSTEPS 257
#define SENC 512
#define ESZ 512
#define MROWS (BSZ*TSTEPS)
#define NB 128
typedef unsigned long long ull;

// ------------- device scratch (statics; no allocations) -------------
__device__ float g_X0[(size_t)MROWS * 4096];      // [t*16+b][gate_row] row-major
__device__ float g_hs[(size_t)MROWS * HSZ];       // [b*257+t][j]
__device__ float g_ctx[(size_t)MROWS * HSZ];
__device__ float g_att[(size_t)MROWS * SENC];
__device__ float g_hidden[(size_t)MROWS * HSZ];
__device__ float g_logits[(size_t)MROWS * HSZ];   // V==1024
__device__ float g_h[3][2][BSZ * HSZ];            // ping-pong hidden per layer
__device__ float g_nll[MROWS];
__device__ int   g_tok[MROWS];                    // dec_in, index t*16+b
__device__ int   g_tgt[MROWS];                    // dec_out, index b*257+t
__device__ unsigned g_barc;

#define FMA2(a,x,y) asm("fma.rn.f32x2 %0, %1, %2, %0;" : "+l"(a) : "l"(x), "l"(y))
__device__ __forceinline__ float sigm(float x){ return 1.f/(1.f+expf(-x)); }

// ------------- init -------------
__global__ void k_init(const int* __restrict__ tokens){
  int i = blockIdx.x*blockDim.x + threadIdx.x;
  if (i == 0) g_barc = 0u;
  if (i < 3*2*BSZ*HSZ) ((float*)g_h)[i] = 0.f;
  if (i < MROWS){
    int t = i / BSZ, b = i % BSZ;
    g_tok[i] = (t == 0) ? 1 : tokens[b*256 + (t-1)];
    int b2 = i / TSTEPS, t2 = i % TSTEPS;
    g_tgt[i] = (t2 < 256) ? tokens[b2*256 + t2] : 2;
  }
}

// ------------- NT GEMM: C = A(MxK) * B(NxK)^T, options -------------
__global__ void __launch_bounds__(256) k_gemm_nt(
    const float* __restrict__ A, int lda, long long sA,
    const float* __restrict__ A2, int lda2, int ksplit, int gather,
    const float* __restrict__ B, int ldb, long long sB,
    float* __restrict__ C, int ldc, long long sC,
    int M, int N, int K, const float* __restrict__ bias, int act)
{
  __shared__ float As[16][68];
  __shared__ float Bs[16][68];
  int z = blockIdx.z;
  const float* Ab = A + (size_t)z * sA;
  const float* Bb = B + (size_t)z * sB;
  float* Cb = C + (size_t)z * sC;
  int m0 = blockIdx.y*64, n0 = blockIdx.x*64;
  int tid = threadIdx.x;
  int tx = tid & 15, ty = tid >> 4;
  float acc[4][4];
#pragma unroll
  for (int i=0;i<4;i++)
#pragma unroll
    for (int j=0;j<4;j++) acc[i][j] = 0.f;

  int r = tid >> 2, c4 = (tid & 3) * 4;

  for (int k0 = 0; k0 < K; k0 += 16){
    float4 va = make_float4(0.f,0.f,0.f,0.f);
    int m = m0 + r;
    if (m < M){
      int kg = k0 + c4;
      int row = gather ? g_tok[m] : m;
      const float* src;
      if (A2 && kg >= ksplit) src = A2 + (size_t)row*lda2 + (kg - ksplit);
      else                    src = Ab + (size_t)row*lda + kg;
      va = *reinterpret_cast<const float4*>(src);
    }
    As[c4+0][r]=va.x; As[c4+1][r]=va.y; As[c4+2][r]=va.z; As[c4+3][r]=va.w;
    float4 vb = *reinterpret_cast<const float4*>(Bb + (size_t)(n0+r)*ldb + k0 + c4);
    Bs[c4+0][r]=vb.x; Bs[c4+1][r]=vb.y; Bs[c4+2][r]=vb.z; Bs[c4+3][r]=vb.w;
    __syncthreads();
#pragma unroll
    for (int kk=0;kk<16;kk++){
      float4 a = *reinterpret_cast<const float4*>(&As[kk][ty*4]);
      float4 b = *reinterpret_cast<const float4*>(&Bs[kk][tx*4]);
      acc[0][0]+=a.x*b.x; acc[0][1]+=a.x*b.y; acc[0][2]+=a.x*b.z; acc[0][3]+=a.x*b.w;
      acc[1][0]+=a.y*b.x; acc[1][1]+=a.y*b.y; acc[1][2]+=a.y*b.z; acc[1][3]+=a.y*b.w;
      acc[2][0]+=a.z*b.x; acc[2][1]+=a.z*b.y; acc[2][2]+=a.z*b.z; acc[2][3]+=a.z*b.w;
      acc[3][0]+=a.w*b.x; acc[3][1]+=a.w*b.y; acc[3][2]+=a.w*b.z; acc[3][3]+=a.w*b.w;
    }
    __syncthreads();
  }
#pragma unroll
  for (int i=0;i<4;i++){
    int m = m0 + ty*4 + i;
    if (m < M){
#pragma unroll
      for (int j=0;j<4;j++){
        int n = n0 + tx*4 + j;
        float v = acc[i][j];
        if (bias) v += bias[n];
        if (act)  v = tanhf(v);
        Cb[(size_t)m*ldc + n] = v;
      }
    }
  }
}

// ------------- NN GEMM: C = A(MxK) * B(KxN) -------------
__global__ void __launch_bounds__(256) k_gemm_nn(
    const float* __restrict__ A, int lda, long long sA,
    const float* __restrict__ B, int ldb, long long sB,
    float* __restrict__ C, int ldc, long long sC,
    int M, int N, int K)
{
  __shared__ float As[16][68];
  __shared__ float Bs[16][68];
  int z = blockIdx.z;
  const float* Ab = A + (size_t)z*sA;
  const float* Bb = B + (size_t)z*sB;
  float* Cb = C + (size_t)z*sC;
  int m0 = blockIdx.y*64, n0 = blockIdx.x*64;
  int tid = threadIdx.x;
  int tx = tid & 15, ty = tid >> 4;
  float acc[4][4];
#pragma unroll
  for (int i=0;i<4;i++)
#pragma unroll
    for (int j=0;j<4;j++) acc[i][j]=0.f;

  int r = tid >> 2, c4 = (tid & 3)*4;
  int kr = tid >> 4, nc4 = (tid & 15)*4;

  for (int k0=0;k0<K;k0+=16){
    float4 va = make_float4(0.f,0.f,0.f,0.f);
    int m = m0 + r;
    if (m < M) va = *reinterpret_cast<const float4*>(Ab + (size_t)m*lda + k0 + c4);
    As[c4+0][r]=va.x; As[c4+1][r]=va.y; As[c4+2][r]=va.z; As[c4+3][r]=va.w;
    float4 vb = *reinterpret_cast<const float4*>(Bb + (size_t)(k0+kr)*ldb + n0 + nc4);
    Bs[kr][nc4+0]=vb.x; Bs[kr][nc4+1]=vb.y; Bs[kr][nc4+2]=vb.z; Bs[kr][nc4+3]=vb.w;
    __syncthreads();
#pragma unroll
    for (int kk=0;kk<16;kk++){
      float4 a = *reinterpret_cast<const float4*>(&As[kk][ty*4]);
      float4 b = *reinterpret_cast<const float4*>(&Bs[kk][tx*4]);
      acc[0][0]+=a.x*b.x; acc[0][1]+=a.x*b.y; acc[0][2]+=a.x*b.z; acc[0][3]+=a.x*b.w;
      acc[1][0]+=a.y*b.x; acc[1][1]+=a.y*b.y; acc[1][2]+=a.y*b.z; acc[1][3]+=a.y*b.w;
      acc[2][0]+=a.z*b.x; acc[2][1]+=a.z*b.y; acc[2][2]+=a.z*b.z; acc[2][3]+=a.z*b.w;
      acc[3][0]+=a.w*b.x; acc[3][1]+=a.w*b.y; acc[3][2]+=a.w*b.z; acc[3][3]+=a.w*b.w;
    }
    __syncthreads();
  }
#pragma unroll
  for (int i=0;i<4;i++){
    int m = m0 + ty*4 + i;
    if (m < M){
#pragma unroll
      for (int j=0;j<4;j++) Cb[(size_t)m*ldc + (n0 + tx*4 + j)] = acc[i][j];
    }
  }
}

// ------------- persistent recurrence (value-validated in R2/R3) -------------
__device__ __forceinline__ void gridbar(unsigned target){
  __threadfence();
  __syncthreads();
  if (threadIdx.x == 0){
    atomicAdd(&g_barc, 1u);
    while (*(volatile unsigned*)&g_barc < target) { }
  }
  __syncthreads();
}

__device__ __forceinline__ void stage_half(const float* __restrict__ src, int kbase, float* buf){
  int tid = threadIdx.x;
#pragma unroll
  for (int i=0;i<8;i++){
    int idx = tid + (i<<8);
    int b = idx >> 7, c = idx & 127;
    ((float4*)buf)[idx] = __ldcg((const float4*)(src + (b<<10) + kbase) + c);
  }
}

__device__ __forceinline__ void dot_half(const float* __restrict__ W, int kbase,
    const float* __restrict__ buf, int ju, int lane, ull acc[4][16])
{
#pragma unroll 4
  for (int m=0;m<8;m++){
    int p = lane + (m<<5);
    ull wv[4];
#pragma unroll
    for (int r=0;r<4;r++)
      wv[r] = __ldcg((const ull*)(W + ((size_t)(ju + (r<<10)))*1024 + kbase + (p<<1)));
#pragma unroll
    for (int b=0;b<16;b++){
      ull hv = *(const ull*)(buf + (b<<9) + (p<<1));
#pragma unroll
      for (int r=0;r<4;r++) FMA2(acc[r][b], wv[r], hv);
    }
  }
}

__device__ __forceinline__ void acc_k1024(const float* W, const float* src,
    float* buf, int ju, int lane, ull acc[4][16])
{
  stage_half(src, 0, buf);   __syncthreads();
  dot_half(W, 0, buf, ju, lane, acc);   __syncthreads();
  stage_half(src, 512, buf); __syncthreads();
  dot_half(W, 512, buf, ju, lane, acc); __syncthreads();
}

__global__ void __launch_bounds__(256,1) k_recur(
    const float* __restrict__ Whh0, const float* __restrict__ bi0, const float* __restrict__ bh0,
    const float* __restrict__ Wih1, const float* __restrict__ Whh1,
    const float* __restrict__ bi1, const float* __restrict__ bh1,
    const float* __restrict__ Wih2, const float* __restrict__ Whh2,
    const float* __restrict__ bi2, const float* __restrict__ bh2)
{
  __shared__ float buf[BSZ*512];
  __shared__ float s_bias[8][3][4];
  int tid = threadIdx.x, lane = tid & 31, wid = tid >> 5;
  int ju = blockIdx.x*8 + wid;

  if (lane < 4){
    int rr = ju + lane*1024;
    s_bias[wid][0][lane] = bi0[rr] + bh0[rr];
    s_bias[wid][1][lane] = bi1[rr] + bh1[rr];
    s_bias[wid][2][lane] = bi2[rr] + bh2[rr];
  }
  __syncthreads();

  float c0=0.f, c1=0.f, c2=0.f;
  unsigned epoch = 0;

  for (int t=0;t<TSTEPS;t++){
    int cur = t & 1, prv = cur ^ 1;
    for (int l=0;l<3;l++){
      ull acc[4][16];
#pragma unroll
      for (int r=0;r<4;r++)
#pragma unroll
        for (int b=0;b<16;b++) acc[r][b] = 0ull;

      const float* Wq[2]; const float* sq[2]; int nq; float* dst;
      if (l==0){ Wq[0]=Whh0; sq[0]=g_h[0][prv]; nq=1; dst=g_h[0][cur]; }
      else if (l==1){ Wq[0]=Wih1; sq[0]=g_h[0][cur]; Wq[1]=Whh1; sq[1]=g_h[1][prv]; nq=2; dst=g_h[1][cur]; }
      else { Wq[0]=Wih2; sq[0]=g_h[1][cur]; Wq[1]=Whh2; sq[1]=g_h[2][prv]; nq=2; dst=g_h[2][cur]; }

      for (int q=0;q<nq;q++) acc_k1024(Wq[q], sq[q], buf, ju, lane, acc);

      // reduce across lanes; gate value for batch b lands in lane b
      float gv[4];
#pragma unroll
      for (int r=0;r<4;r++){
        float keep = 0.f;
#pragma unroll
        for (int b=0;b<16;b++){
          ull v = acc[r][b];
          float s = __uint_as_float((unsigned)v) + __uint_as_float((unsigned)(v>>32));
          s += __shfl_xor_sync(0xffffffffu, s, 16);
          s += __shfl_xor_sync(0xffffffffu, s, 8);
          s += __shfl_xor_sync(0xffffffffu, s, 4);
          s += __shfl_xor_sync(0xffffffffu, s, 2);
          s += __shfl_xor_sync(0xffffffffu, s, 1);
          keep = (lane == b) ? s : keep;
        }
        gv[r] = keep + s_bias[wid][l][r];
      }

      if (lane < 16){
        if (l == 0){
#pragma unroll
          for (int r=0;r<4;r++)
            gv[r] += g_X0[((size_t)(t*BSZ + lane))*4096 + ju + (r<<10)];
        }
        float c = (l==0) ? c0 : ((l==1) ? c1 : c2);
        float iv = sigm(gv[0]), fv = sigm(gv[1]);
        float gg = tanhf(gv[2]), ov = sigm(gv[3]);
        c = fv*c + iv*gg;
        float h = ov * tanhf(c);
        if (l==0) c0=c; else if (l==1) c1=c; else c2=c;
        dst[lane*HSZ + ju] = h;
        if (l == 2) g_hs[((size_t)lane*TSTEPS + t)*HSZ + ju] = h;
      }
      epoch++;
      gridbar(epoch * NB);
    }
  }
}

// ------------- softmax over S=512 -------------
__global__ void k_softmax(){
  int m = blockIdx.x;
  float* row = g_att + (size_t)m * SENC;
  int tid = threadIdx.x;            // 128
  __shared__ float sm[4];
  float v[4];
#pragma unroll
  for (int i=0;i<4;i++) v[i] = row[tid + 128*i];
  float mx = fmaxf(fmaxf(v[0],v[1]), fmaxf(v[2],v[3]));
#pragma unroll
  for (int o=16;o>0;o>>=1) mx = fmaxf(mx, __shfl_xor_sync(0xffffffffu, mx, o));
  if ((tid & 31) == 0) sm[tid>>5] = mx;
  __syncthreads();
  mx = fmaxf(fmaxf(sm[0],sm[1]), fmaxf(sm[2],sm[3]));
  float s = 0.f;
#pragma unroll
  for (int i=0;i<4;i++){ v[i] = expf(v[i]-mx); s += v[i]; }
#pragma unroll
  for (int o=16;o>0;o>>=1) s += __shfl_xor_sync(0xffffffffu, s, o);
  __syncthreads();
  if ((tid & 31) == 0) sm[tid>>5] = s;
  __syncthreads();
  s = sm[0]+sm[1]+sm[2]+sm[3];
  float inv = 1.f / s;
#pragma unroll
  for (int i=0;i<4;i++) row[tid + 128*i] = v[i]*inv;
}

// ------------- NLL over V=1024 -------------
__global__ void k_nll(){
  int m = blockIdx.x;
  const float* row = g_logits + (size_t)m * 1024;
  int tid = threadIdx.x;            // 256
  __shared__ float sm[8];
  float v[4];
#pragma unroll
  for (int i=0;i<4;i++) v[i] = row[tid + 256*i];
  float mx = fmaxf(fmaxf(v[0],v[1]), fmaxf(v[2],v[3]));
#pragma unroll
  for (int o=16;o>0;o>>=1) mx = fmaxf(mx, __shfl_xor_sync(0xffffffffu, mx, o));
  if ((tid & 31) == 0) sm[tid>>5] = mx;
  __syncthreads();
  mx = sm[0];
#pragma unroll
  for (int i=1;i<8;i++) mx = fmaxf(mx, sm[i]);
  float s = 0.f;
#pragma unroll
  for (int i=0;i<4;i++) s += expf(v[i]-mx);
#pragma unroll
  for (int o=16;o>0;o>>=1) s += __shfl_xor_sync(0xffffffffu, s, o);
  __syncthreads();
  if ((tid & 31) == 0) sm[tid>>5] = s;
  __syncthreads();
  if (tid == 0){
    float tot = 0.f;
#pragma unroll
    for (int i=0;i<8;i++) tot += sm[i];
    g_nll[m] = (logf(tot) + mx) - row[g_tgt[m]];
  }
}

__global__ void k_final(float* __restrict__ out){
  int tid = threadIdx.x;            // 256
  __shared__ float sm[8];
  float s = 0.f;
  for (int i=tid; i<MROWS; i+=256) s += g_nll[i];
#pragma unroll
  for (int o=16;o>0;o>>=1) s += __shfl_xor_sync(0xffffffffu, s, o);
  if ((tid & 31) == 0) sm[tid>>5] = s;
  __syncthreads();
  if (tid == 0){
    float tot = 0.f;
#pragma unroll
    for (int i=0;i<8;i++) tot += sm[i];
    out[0] = tot / (float)MROWS;
  }
}

// ------------- launcher -------------
extern "C" void kernel_launch(void* const* d_in, const int* in_sizes, int n_in,
                              void* d_out, int out_size)
{
  const int*   tokens = (const int*)  d_in[0];
  const float* enc    = (const float*)d_in[1];
  const float* emb    = (const float*)d_in[2];   // (1024, 512): E = 512
  const float* Wih0   = (const float*)d_in[3];   // (4096, 1536)
  const float* Whh0   = (const float*)d_in[4];
  const float* bi0    = (const float*)d_in[5];
  const float* bh0    = (const float*)d_in[6];
  const float* Wih1   = (const float*)d_in[7];
  const float* Whh1   = (const float*)d_in[8];
  const float* bi1    = (const float*)d_in[9];
  const float* bh1    = (const float*)d_in[10];
  const float* Wih2   = (const float*)d_in[11];
  const float* Whh2   = (const float*)d_in[12];
  const float* bi2    = (const float*)d_in[13];
  const float* bh2    = (const float*)d_in[14];
  const float* W1     = (const float*)d_in[15];
  const float* b1     = (const float*)d_in[16];
  const float* W2     = (const float*)d_in[17];
  const float* b2     = (const float*)d_in[18];
  float* out = (float*)d_out;

  void *pX0,*pHS,*pCTX,*pATT,*pHID,*pLOG;
  cudaGetSymbolAddress(&pX0,  g_X0);
  cudaGetSymbolAddress(&pHS,  g_hs);
  cudaGetSymbolAddress(&pCTX, g_ctx);
  cudaGetSymbolAddress(&pATT, g_att);
  cudaGetSymbolAddress(&pHID, g_hidden);
  cudaGetSymbolAddress(&pLOG, g_logits);
  float* X0 = (float*)pX0;

  k_init<<<384,256>>>(tokens);

  // X0[4112, 4096] = gather(emb)[.,512] @ W_ih0[:, :512]^T (lda=512, ldb=1536, K=512)
  k_gemm_nt<<<dim3(64,65,1),256>>>(emb,ESZ,0, nullptr,ESZ,1<<30, 1,
                                   Wih0,1536,0, X0, 4096,0,
                                   MROWS,4096,ESZ, nullptr,0);

  k_recur<<<NB,256>>>(Whh0,bi0,bh0, Wih1,Whh1,bi1,bh1, Wih2,Whh2,bi2,bh2);

  // scores[b]: hs[b] (257x1024) @ enc[b]^T (512x1024)
  k_gemm_nt<<<dim3(8,5,16),256>>>((const float*)pHS,1024,257LL*1024, nullptr,1024,1<<30, 0,
                                  enc,1024,512LL*1024, (float*)pATT,512,257LL*512,
                                  257,512,1024, nullptr,0);

  k_softmax<<<MROWS,128>>>();

  // ctx[b]: attn[b] (257x512) @ enc[b] (512x1024)
  k_gemm_nn<<<dim3(16,5,16),256>>>((const float*)pATT,512,257LL*512,
                                   enc,1024,512LL*1024,
                                   (float*)pCTX,1024,257LL*1024, 257,1024,512);

  // hidden = tanh([hs|ctx] @ W1^T + b1)
  k_gemm_nt<<<dim3(16,65,1),256>>>((const float*)pHS,1024,0, (const float*)pCTX,1024,1024, 0,
                                   W1,2048,0, (float*)pHID,1024,0,
                                   MROWS,1024,2048, b1,1);

  // logits = hidden @ W2^T + b2
  k_gemm_nt<<<dim3(16,65,1),256>>>((const float*)pHID,1024,0, nullptr,1024,1<<30, 0,
                                   W2,1024,0, (float*)pLOG,1024,0,
                                   MROWS,1024,1024, b2,0);

  k_nll<<<MROWS,256>>>();
  k_final<<<1,256>>>(out);
}

// round 7
// speedup vs baseline: 2.0466x; 1.0328x over previous
#include <cuda_runtime.h>
#include <cstdint>
#include <cstddef>

#define HSZ 1024
#define BSZ 16
#define TSTEPS 257
#define SENC 512
#define ESZ 512
#define MROWS (BSZ*TSTEPS)
#define NB 128
typedef unsigned long long ull;

// ------------- device scratch (statics; no allocations) -------------
__device__ float g_X0[(size_t)MROWS * 4096];      // [t*16+b][gate_row] row-major
__device__ float g_hs[(size_t)MROWS * HSZ];       // [b*257+t][j]
__device__ float g_ctx[(size_t)MROWS * HSZ];
__device__ float g_att[(size_t)MROWS * SENC];
__device__ float g_hidden[(size_t)MROWS * HSZ];
__device__ float g_logits[(size_t)MROWS * HSZ];   // V==1024
__device__ float g_h[3][2][BSZ * HSZ];            // ping-pong hidden per layer
__device__ float g_nll[MROWS];
__device__ int   g_tok[MROWS];                    // dec_in, index t*16+b
__device__ int   g_tgt[MROWS];                    // dec_out, index b*257+t
__device__ unsigned g_barc;

#define FMA2(a,x,y) asm("fma.rn.f32x2 %0, %1, %2, %0;" : "+l"(a) : "l"(x), "l"(y))
__device__ __forceinline__ float sigm(float x){ return 1.f/(1.f+expf(-x)); }

// ------------- init -------------
__global__ void k_init(const int* __restrict__ tokens){
  int i = blockIdx.x*blockDim.x + threadIdx.x;
  if (i == 0) g_barc = 0u;
  if (i < 3*2*BSZ*HSZ) ((float*)g_h)[i] = 0.f;
  if (i < MROWS){
    int t = i / BSZ, b = i % BSZ;
    g_tok[i] = (t == 0) ? 1 : tokens[b*256 + (t-1)];
    int b2 = i / TSTEPS, t2 = i % TSTEPS;
    g_tgt[i] = (t2 < 256) ? tokens[b2*256 + t2] : 2;
  }
}

// ------------- NT GEMM: C = A(MxK) * B(NxK)^T, options -------------
__global__ void __launch_bounds__(256) k_gemm_nt(
    const float* __restrict__ A, int lda, long long sA,
    const float* __restrict__ A2, int lda2, int ksplit, int gather,
    const float* __restrict__ B, int ldb, long long sB,
    float* __restrict__ C, int ldc, long long sC,
    int M, int N, int K, const float* __restrict__ bias, int act)
{
  __shared__ float As[16][68];
  __shared__ float Bs[16][68];
  int z = blockIdx.z;
  const float* Ab = A + (size_t)z * sA;
  const float* Bb = B + (size_t)z * sB;
  float* Cb = C + (size_t)z * sC;
  int m0 = blockIdx.y*64, n0 = blockIdx.x*64;
  int tid = threadIdx.x;
  int tx = tid & 15, ty = tid >> 4;
  float acc[4][4];
#pragma unroll
  for (int i=0;i<4;i++)
#pragma unroll
    for (int j=0;j<4;j++) acc[i][j] = 0.f;

  int r = tid >> 2, c4 = (tid & 3) * 4;

  for (int k0 = 0; k0 < K; k0 += 16){
    float4 va = make_float4(0.f,0.f,0.f,0.f);
    int m = m0 + r;
    if (m < M){
      int kg = k0 + c4;
      int row = gather ? g_tok[m] : m;
      const float* src;
      if (A2 && kg >= ksplit) src = A2 + (size_t)row*lda2 + (kg - ksplit);
      else                    src = Ab + (size_t)row*lda + kg;
      va = *reinterpret_cast<const float4*>(src);
    }
    As[c4+0][r]=va.x; As[c4+1][r]=va.y; As[c4+2][r]=va.z; As[c4+3][r]=va.w;
    float4 vb = *reinterpret_cast<const float4*>(Bb + (size_t)(n0+r)*ldb + k0 + c4);
    Bs[c4+0][r]=vb.x; Bs[c4+1][r]=vb.y; Bs[c4+2][r]=vb.z; Bs[c4+3][r]=vb.w;
    __syncthreads();
#pragma unroll
    for (int kk=0;kk<16;kk++){
      float4 a = *reinterpret_cast<const float4*>(&As[kk][ty*4]);
      float4 b = *reinterpret_cast<const float4*>(&Bs[kk][tx*4]);
      acc[0][0]+=a.x*b.x; acc[0][1]+=a.x*b.y; acc[0][2]+=a.x*b.z; acc[0][3]+=a.x*b.w;
      acc[1][0]+=a.y*b.x; acc[1][1]+=a.y*b.y; acc[1][2]+=a.y*b.z; acc[1][3]+=a.y*b.w;
      acc[2][0]+=a.z*b.x; acc[2][1]+=a.z*b.y; acc[2][2]+=a.z*b.z; acc[2][3]+=a.z*b.w;
      acc[3][0]+=a.w*b.x; acc[3][1]+=a.w*b.y; acc[3][2]+=a.w*b.z; acc[3][3]+=a.w*b.w;
    }
    __syncthreads();
  }
#pragma unroll
  for (int i=0;i<4;i++){
    int m = m0 + ty*4 + i;
    if (m < M){
#pragma unroll
      for (int j=0;j<4;j++){
        int n = n0 + tx*4 + j;
        float v = acc[i][j];
        if (bias) v += bias[n];
        if (act)  v = tanhf(v);
        Cb[(size_t)m*ldc + n] = v;
      }
    }
  }
}

// ------------- NN GEMM: C = A(MxK) * B(KxN) -------------
__global__ void __launch_bounds__(256) k_gemm_nn(
    const float* __restrict__ A, int lda, long long sA,
    const float* __restrict__ B, int ldb, long long sB,
    float* __restrict__ C, int ldc, long long sC,
    int M, int N, int K)
{
  __shared__ float As[16][68];
  __shared__ float Bs[16][68];
  int z = blockIdx.z;
  const float* Ab = A + (size_t)z*sA;
  const float* Bb = B + (size_t)z*sB;
  float* Cb = C + (size_t)z*sC;
  int m0 = blockIdx.y*64, n0 = blockIdx.x*64;
  int tid = threadIdx.x;
  int tx = tid & 15, ty = tid >> 4;
  float acc[4][4];
#pragma unroll
  for (int i=0;i<4;i++)
#pragma unroll
    for (int j=0;j<4;j++) acc[i][j]=0.f;

  int r = tid >> 2, c4 = (tid & 3)*4;
  int kr = tid >> 4, nc4 = (tid & 15)*4;

  for (int k0=0;k0<K;k0+=16){
    float4 va = make_float4(0.f,0.f,0.f,0.f);
    int m = m0 + r;
    if (m < M) va = *reinterpret_cast<const float4*>(Ab + (size_t)m*lda + k0 + c4);
    As[c4+0][r]=va.x; As[c4+1][r]=va.y; As[c4+2][r]=va.z; As[c4+3][r]=va.w;
    float4 vb = *reinterpret_cast<const float4*>(Bb + (size_t)(k0+kr)*ldb + n0 + nc4);
    Bs[kr][nc4+0]=vb.x; Bs[kr][nc4+1]=vb.y; Bs[kr][nc4+2]=vb.z; Bs[kr][nc4+3]=vb.w;
    __syncthreads();
#pragma unroll
    for (int kk=0;kk<16;kk++){
      float4 a = *reinterpret_cast<const float4*>(&As[kk][ty*4]);
      float4 b = *reinterpret_cast<const float4*>(&Bs[kk][tx*4]);
      acc[0][0]+=a.x*b.x; acc[0][1]+=a.x*b.y; acc[0][2]+=a.x*b.z; acc[0][3]+=a.x*b.w;
      acc[1][0]+=a.y*b.x; acc[1][1]+=a.y*b.y; acc[1][2]+=a.y*b.z; acc[1][3]+=a.y*b.w;
      acc[2][0]+=a.z*b.x; acc[2][1]+=a.z*b.y; acc[2][2]+=a.z*b.z; acc[2][3]+=a.z*b.w;
      acc[3][0]+=a.w*b.x; acc[3][1]+=a.w*b.y; acc[3][2]+=a.w*b.z; acc[3][3]+=a.w*b.w;
    }
    __syncthreads();
  }
#pragma unroll
  for (int i=0;i<4;i++){
    int m = m0 + ty*4 + i;
    if (m < M){
#pragma unroll
      for (int j=0;j<4;j++) Cb[(size_t)m*ldc + (n0 + tx*4 + j)] = acc[i][j];
    }
  }
}

// ------------- persistent wavefront recurrence -------------
__device__ __forceinline__ void gridbar(unsigned target){
  __threadfence();
  __syncthreads();
  if (threadIdx.x == 0){
    atomicAdd(&g_barc, 1u);
    while (*(volatile unsigned*)&g_barc < target) { }
  }
  __syncthreads();
}

// stage one K-half (16 batches x 512 floats = 32KB) with 512 threads
__device__ __forceinline__ void stage_half(const float* __restrict__ src, int kbase, float* buf){
  int tid = threadIdx.x;
#pragma unroll
  for (int i=0;i<4;i++){
    int idx = tid + (i<<9);
    int b = idx >> 7, c = idx & 127;
    ((float4*)buf)[idx] = __ldcg((const float4*)(src + (b<<10) + kbase) + c);
  }
}

// dot over one K-half: warp = unit ju, 4 gate rows, batches [B0, B0+8)
__device__ __forceinline__ void dot_half(const float* __restrict__ W, int kbase,
    const float* __restrict__ buf, int ju, int lane, int B0, ull acc[4][8])
{
#pragma unroll 4
  for (int m=0;m<8;m++){
    int p = lane + (m<<5);
    ull wv[4];
#pragma unroll
    for (int r=0;r<4;r++)
      wv[r] = __ldcg((const ull*)(W + ((size_t)(ju + (r<<10)))*1024 + kbase + (p<<1)));
#pragma unroll
    for (int bb=0;bb<8;bb++){
      ull hv = *(const ull*)(buf + ((size_t)(B0+bb)<<9) + (p<<1));
#pragma unroll
      for (int r=0;r<4;r++) FMA2(acc[r][bb], wv[r], hv);
    }
  }
}

__device__ __forceinline__ void acc_k1024(const float* W, const float* src,
    float* buf, int ju, int lane, int B0, ull acc[4][8])
{
  __syncthreads();
  stage_half(src, 0, buf);   __syncthreads();
  dot_half(W, 0, buf, ju, lane, B0, acc);
  __syncthreads();
  stage_half(src, 512, buf); __syncthreads();
  dot_half(W, 512, buf, ju, lane, B0, acc);
}

// butterfly reduce: 32 per-lane partials (index r*8+bb) -> lane (r*8+bb) holds full sum
__device__ __forceinline__ float reduce32(ull acc[4][8], int lane){
  float v[32];
#pragma unroll
  for (int r=0;r<4;r++)
#pragma unroll
    for (int bb=0;bb<8;bb++){
      ull x = acc[r][bb];
      v[r*8+bb] = __uint_as_float((unsigned)x) + __uint_as_float((unsigned)(x>>32));
    }
#pragma unroll
  for (int off=16; off>=1; off>>=1){
    int n = off;
#pragma unroll
    for (int i=0;i<16;i++){
      if (i < n){
        float a = (lane & off) ? v[i+n] : v[i];
        float b = (lane & off) ? v[i]   : v[i+n];
        v[i] = a + __shfl_xor_sync(0xffffffffu, b, off);
      }
    }
  }
  return v[0];
}

__global__ void __launch_bounds__(512,1) k_recur(
    const float* __restrict__ Whh0, const float* __restrict__ bi0, const float* __restrict__ bh0,
    const float* __restrict__ Wih1, const float* __restrict__ Whh1,
    const float* __restrict__ bi1, const float* __restrict__ bh1,
    const float* __restrict__ Wih2, const float* __restrict__ Whh2,
    const float* __restrict__ bi2, const float* __restrict__ bh2)
{
  __shared__ float buf[BSZ*512];
  int tid = threadIdx.x, lane = tid & 31, wid = tid >> 5;
  int ju = blockIdx.x*8 + (wid >> 1);     // unit owned by this warp
  int B0 = (wid & 1) * 8;                 // batch half
  int myr = lane >> 3, mybb = lane & 7;   // this lane's (gate row, batch-in-half)

  float bias0, bias1, bias2;
  {
    int rr = (myr<<10) + ju;
    bias0 = bi0[rr] + bh0[rr];
    bias1 = bi1[rr] + bh1[rr];
    bias2 = bi2[rr] + bh2[rr];
  }

  float c0 = 0.f, c1 = 0.f, c2 = 0.f;    // cell state (valid in lanes 0-7)
  unsigned epoch = 0;

  for (int p = 0; p < TSTEPS + 2; p++){
    // ---------- layer 0, t = p ----------
    if (p < TSTEPS){
      int t = p;
      ull acc[4][8];
#pragma unroll
      for (int r=0;r<4;r++)
#pragma unroll
        for (int bb=0;bb<8;bb++) acc[r][bb] = 0ull;
      acc_k1024(Whh0, g_h[0][(t+1)&1], buf, ju, lane, B0, acc);
      float g = reduce32(acc, lane) + bias0;
      g += __ldcg(&g_X0[((size_t)(t*BSZ + B0 + mybb))*4096 + (myr<<10) + ju]);
      float gi = __shfl_sync(0xffffffffu, g, mybb);
      float gf = __shfl_sync(0xffffffffu, g, 8 + mybb);
      float gg = __shfl_sync(0xffffffffu, g, 16 + mybb);
      float go = __shfl_sync(0xffffffffu, g, 24 + mybb);
      if (lane < 8){
        float iv=sigm(gi), fv=sigm(gf), gv=tanhf(gg), ov=sigm(go);
        c0 = fv*c0 + iv*gv;
        g_h[0][t&1][((B0+lane)<<10) + ju] = ov * tanhf(c0);
      }
    }
    // ---------- layer 1, t = p-1 ----------
    if (p >= 1 && p <= TSTEPS){
      int t = p - 1;
      ull acc[4][8];
#pragma unroll
      for (int r=0;r<4;r++)
#pragma unroll
        for (int bb=0;bb<8;bb++) acc[r][bb] = 0ull;
      acc_k1024(Wih1, g_h[0][t&1],     buf, ju, lane, B0, acc);
      acc_k1024(Whh1, g_h[1][(t+1)&1], buf, ju, lane, B0, acc);
      float g = reduce32(acc, lane) + bias1;
      float gi = __shfl_sync(0xffffffffu, g, mybb);
      float gf = __shfl_sync(0xffffffffu, g, 8 + mybb);
      float gg = __shfl_sync(0xffffffffu, g, 16 + mybb);
      float go = __shfl_sync(0xffffffffu, g, 24 + mybb);
      if (lane < 8){
        float iv=sigm(gi), fv=sigm(gf), gv=tanhf(gg), ov=sigm(go);
        c1 = fv*c1 + iv*gv;
        g_h[1][t&1][((B0+lane)<<10) + ju] = ov * tanhf(c1);
      }
    }
    // ---------- layer 2, t = p-2 ----------
    if (p >= 2){
      int t = p - 2;
      ull acc[4][8];
#pragma unroll
      for (int r=0;r<4;r++)
#pragma unroll
        for (int bb=0;bb<8;bb++) acc[r][bb] = 0ull;
      acc_k1024(Wih2, g_h[1][t&1],     buf, ju, lane, B0, acc);
      acc_k1024(Whh2, g_h[2][(t+1)&1], buf, ju, lane, B0, acc);
      float g = reduce32(acc, lane) + bias2;
      float gi = __shfl_sync(0xffffffffu, g, mybb);
      float gf = __shfl_sync(0xffffffffu, g, 8 + mybb);
      float gg = __shfl_sync(0xffffffffu, g, 16 + mybb);
      float go = __shfl_sync(0xffffffffu, g, 24 + mybb);
      if (lane < 8){
        float iv=sigm(gi), fv=sigm(gf), gv=tanhf(gg), ov=sigm(go);
        c2 = fv*c2 + iv*gv;
        float h = ov * tanhf(c2);
        int b = B0 + lane;
        g_h[2][t&1][(b<<10) + ju] = h;
        g_hs[((size_t)b*TSTEPS + t)*HSZ + ju] = h;
      }
    }
    epoch++;
    gridbar(epoch * NB);
  }
}

// ------------- softmax over S=512 -------------
__global__ void k_softmax(){
  int m = blockIdx.x;
  float* row = g_att + (size_t)m * SENC;
  int tid = threadIdx.x;            // 128
  __shared__ float sm[4];
  float v[4];
#pragma unroll
  for (int i=0;i<4;i++) v[i] = row[tid + 128*i];
  float mx = fmaxf(fmaxf(v[0],v[1]), fmaxf(v[2],v[3]));
#pragma unroll
  for (int o=16;o>0;o>>=1) mx = fmaxf(mx, __shfl_xor_sync(0xffffffffu, mx, o));
  if ((tid & 31) == 0) sm[tid>>5] = mx;
  __syncthreads();
  mx = fmaxf(fmaxf(sm[0],sm[1]), fmaxf(sm[2],sm[3]));
  float s = 0.f;
#pragma unroll
  for (int i=0;i<4;i++){ v[i] = expf(v[i]-mx); s += v[i]; }
#pragma unroll
  for (int o=16;o>0;o>>=1) s += __shfl_xor_sync(0xffffffffu, s, o);
  __syncthreads();
  if ((tid & 31) == 0) sm[tid>>5] = s;
  __syncthreads();
  s = sm[0]+sm[1]+sm[2]+sm[3];
  float inv = 1.f / s;
#pragma unroll
  for (int i=0;i<4;i++) row[tid + 128*i] = v[i]*inv;
}

// ------------- NLL over V=1024 -------------
__global__ void k_nll(){
  int m = blockIdx.x;
  const float* row = g_logits + (size_t)m * 1024;
  int tid = threadIdx.x;            // 256
  __shared__ float sm[8];
  float v[4];
#pragma unroll
  for (int i=0;i<4;i++) v[i] = row[tid + 256*i];
  float mx = fmaxf(fmaxf(v[0],v[1]), fmaxf(v[2],v[3]));
#pragma unroll
  for (int o=16;o>0;o>>=1) mx = fmaxf(mx, __shfl_xor_sync(0xffffffffu, mx, o));
  if ((tid & 31) == 0) sm[tid>>5] = mx;
  __syncthreads();
  mx = sm[0];
#pragma unroll
  for (int i=1;i<8;i++) mx = fmaxf(mx, sm[i]);
  float s = 0.f;
#pragma unroll
  for (int i=0;i<4;i++) s += expf(v[i]-mx);
#pragma unroll
  for (int o=16;o>0;o>>=1) s += __shfl_xor_sync(0xffffffffu, s, o);
  __syncthreads();
  if ((tid & 31) == 0) sm[tid>>5] = s;
  __syncthreads();
  if (tid == 0){
    float tot = 0.f;
#pragma unroll
    for (int i=0;i<8;i++) tot += sm[i];
    g_nll[m] = (logf(tot) + mx) - row[g_tgt[m]];
  }
}

__global__ void k_final(float* __restrict__ out){
  int tid = threadIdx.x;            // 256
  __shared__ float sm[8];
  float s = 0.f;
  for (int i=tid; i<MROWS; i+=256) s += g_nll[i];
#pragma unroll
  for (int o=16;o>0;o>>=1) s += __shfl_xor_sync(0xffffffffu, s, o);
  if ((tid & 31) == 0) sm[tid>>5] = s;
  __syncthreads();
  if (tid == 0){
    float tot = 0.f;
#pragma unroll
    for (int i=0;i<8;i++) tot += sm[i];
    out[0] = tot / (float)MROWS;
  }
}

// ------------- launcher -------------
extern "C" void kernel_launch(void* const* d_in, const int* in_sizes, int n_in,
                              void* d_out, int out_size)
{
  const int*   tokens = (const int*)  d_in[0];
  const float* enc    = (const float*)d_in[1];
  const float* emb    = (const float*)d_in[2];   // (1024, 512): E = 512
  const float* Wih0   = (const float*)d_in[3];   // (4096, 1536)
  const float* Whh0   = (const float*)d_in[4];
  const float* bi0    = (const float*)d_in[5];
  const float* bh0    = (const float*)d_in[6];
  const float* Wih1   = (const float*)d_in[7];
  const float* Whh1   = (const float*)d_in[8];
  const float* bi1    = (const float*)d_in[9];
  const float* bh1    = (const float*)d_in[10];
  const float* Wih2   = (const float*)d_in[11];
  const float* Whh2   = (const float*)d_in[12];
  const float* bi2    = (const float*)d_in[13];
  const float* bh2    = (const float*)d_in[14];
  const float* W1     = (const float*)d_in[15];
  const float* b1     = (const float*)d_in[16];
  const float* W2     = (const float*)d_in[17];
  const float* b2     = (const float*)d_in[18];
  float* out = (float*)d_out;

  void *pX0,*pHS,*pCTX,*pATT,*pHID,*pLOG;
  cudaGetSymbolAddress(&pX0,  g_X0);
  cudaGetSymbolAddress(&pHS,  g_hs);
  cudaGetSymbolAddress(&pCTX, g_ctx);
  cudaGetSymbolAddress(&pATT, g_att);
  cudaGetSymbolAddress(&pHID, g_hidden);
  cudaGetSymbolAddress(&pLOG, g_logits);
  float* X0 = (float*)pX0;

  k_init<<<384,256>>>(tokens);

  // X0[4112, 4096] = gather(emb)[.,512] @ W_ih0[:, :512]^T (lda=512, ldb=1536, K=512)
  k_gemm_nt<<<dim3(64,65,1),256>>>(emb,ESZ,0, nullptr,ESZ,1<<30, 1,
                                   Wih0,1536,0, X0, 4096,0,
                                   MROWS,4096,ESZ, nullptr,0);

  k_recur<<<NB,512>>>(Whh0,bi0,bh0, Wih1,Whh1,bi1,bh1, Wih2,Whh2,bi2,bh2);

  // scores[b]: hs[b] (257x1024) @ enc[b]^T (512x1024)
  k_gemm_nt<<<dim3(8,5,16),256>>>((const float*)pHS,1024,257LL*1024, nullptr,1024,1<<30, 0,
                                  enc,1024,512LL*1024, (float*)pATT,512,257LL*512,
                                  257,512,1024, nullptr,0);

  k_softmax<<<MROWS,128>>>();

  // ctx[b]: attn[b] (257x512) @ enc[b] (512x1024)
  k_gemm_nn<<<dim3(16,5,16),256>>>((const float*)pATT,512,257LL*512,
                                   enc,1024,512LL*1024,
                                   (float*)pCTX,1024,257LL*1024, 257,1024,512);

  // hidden = tanh([hs|ctx] @ W1^T + b1)
  k_gemm_nt<<<dim3(16,65,1),256>>>((const float*)pHS,1024,0, (const float*)pCTX,1024,1024, 0,
                                   W1,2048,0, (float*)pHID,1024,0,
                                   MROWS,1024,2048, b1,1);

  // logits = hidden @ W2^T + b2
  k_gemm_nt<<<dim3(16,65,1),256>>>((const float*)pHID,1024,0, nullptr,1024,1<<30, 0,
                                   W2,1024,0, (float*)pLOG,1024,0,
                                   MROWS,1024,1024, b2,0);

  k_nll<<<MROWS,256>>>();
  k_final<<<1,256>>>(out);
}

// round 9
// speedup vs baseline: 2.1512x; 1.0511x over previous
#include <cuda_runtime.h>
#include <cstdint>
#include <cstddef>

#define HSZ 1024
#define BSZ 16
#define TSTEPS 257
#define SENC 512
#define ESZ 512
#define MROWS (BSZ*TSTEPS)
#define NB 128
typedef unsigned long long ull;

// ------------- device scratch (statics; no allocations) -------------
__device__ float g_X0[(size_t)MROWS * 4096];      // [t*16+b][gate_row] row-major
__device__ float g_hs[(size_t)MROWS * HSZ];       // [b*257+t][j]
__device__ float g_ctx[(size_t)MROWS * HSZ];
__device__ float g_att[(size_t)MROWS * SENC];
__device__ float g_hidden[(size_t)MROWS * HSZ];
__device__ float g_logits[(size_t)MROWS * HSZ];   // V==1024
__device__ float g_h[3][2][BSZ * HSZ];            // ping-pong hidden per layer
__device__ float g_nll[MROWS];
__device__ int   g_tok[MROWS];                    // dec_in, index t*16+b
__device__ int   g_tgt[MROWS];                    // dec_out, index b*257+t
__device__ unsigned g_barc;

#define FMA2(a,x,y) asm("fma.rn.f32x2 %0, %1, %2, %0;" : "+l"(a) : "l"(x), "l"(y))
__device__ __forceinline__ float sigm(float x){ return 1.f/(1.f+expf(-x)); }

// ------------- init -------------
__global__ void k_init(const int* __restrict__ tokens){
  int i = blockIdx.x*blockDim.x + threadIdx.x;
  if (i == 0) g_barc = 0u;
  if (i < 3*2*BSZ*HSZ) ((float*)g_h)[i] = 0.f;
  if (i < MROWS){
    int t = i / BSZ, b = i % BSZ;
    g_tok[i] = (t == 0) ? 1 : tokens[b*256 + (t-1)];
    int b2 = i / TSTEPS, t2 = i % TSTEPS;
    g_tgt[i] = (t2 < 256) ? tokens[b2*256 + t2] : 2;
  }
}

// ------------- NT GEMM: C = A(MxK) * B(NxK)^T, options -------------
__global__ void __launch_bounds__(256) k_gemm_nt(
    const float* __restrict__ A, int lda, long long sA,
    const float* __restrict__ A2, int lda2, int ksplit, int gather,
    const float* __restrict__ B, int ldb, long long sB,
    float* __restrict__ C, int ldc, long long sC,
    int M, int N, int K, const float* __restrict__ bias, int act)
{
  __shared__ float As[16][68];
  __shared__ float Bs[16][68];
  int z = blockIdx.z;
  const float* Ab = A + (size_t)z * sA;
  const float* Bb = B + (size_t)z * sB;
  float* Cb = C + (size_t)z * sC;
  int m0 = blockIdx.y*64, n0 = blockIdx.x*64;
  int tid = threadIdx.x;
  int tx = tid & 15, ty = tid >> 4;
  float acc[4][4];
#pragma unroll
  for (int i=0;i<4;i++)
#pragma unroll
    for (int j=0;j<4;j++) acc[i][j] = 0.f;

  int r = tid >> 2, c4 = (tid & 3) * 4;

  for (int k0 = 0; k0 < K; k0 += 16){
    float4 va = make_float4(0.f,0.f,0.f,0.f);
    int m = m0 + r;
    if (m < M){
      int kg = k0 + c4;
      int row = gather ? g_tok[m] : m;
      const float* src;
      if (A2 && kg >= ksplit) src = A2 + (size_t)row*lda2 + (kg - ksplit);
      else                    src = Ab + (size_t)row*lda + kg;
      va = *reinterpret_cast<const float4*>(src);
    }
    As[c4+0][r]=va.x; As[c4+1][r]=va.y; As[c4+2][r]=va.z; As[c4+3][r]=va.w;
    float4 vb = *reinterpret_cast<const float4*>(Bb + (size_t)(n0+r)*ldb + k0 + c4);
    Bs[c4+0][r]=vb.x; Bs[c4+1][r]=vb.y; Bs[c4+2][r]=vb.z; Bs[c4+3][r]=vb.w;
    __syncthreads();
#pragma unroll
    for (int kk=0;kk<16;kk++){
      float4 a = *reinterpret_cast<const float4*>(&As[kk][ty*4]);
      float4 b = *reinterpret_cast<const float4*>(&Bs[kk][tx*4]);
      acc[0][0]+=a.x*b.x; acc[0][1]+=a.x*b.y; acc[0][2]+=a.x*b.z; acc[0][3]+=a.x*b.w;
      acc[1][0]+=a.y*b.x; acc[1][1]+=a.y*b.y; acc[1][2]+=a.y*b.z; acc[1][3]+=a.y*b.w;
      acc[2][0]+=a.z*b.x; acc[2][1]+=a.z*b.y; acc[2][2]+=a.z*b.z; acc[2][3]+=a.z*b.w;
      acc[3][0]+=a.w*b.x; acc[3][1]+=a.w*b.y; acc[3][2]+=a.w*b.z; acc[3][3]+=a.w*b.w;
    }
    __syncthreads();
  }
#pragma unroll
  for (int i=0;i<4;i++){
    int m = m0 + ty*4 + i;
    if (m < M){
#pragma unroll
      for (int j=0;j<4;j++){
        int n = n0 + tx*4 + j;
        float v = acc[i][j];
        if (bias) v += bias[n];
        if (act)  v = tanhf(v);
        Cb[(size_t)m*ldc + n] = v;
      }
    }
  }
}

// ------------- NN GEMM: C = A(MxK) * B(KxN) -------------
__global__ void __launch_bounds__(256) k_gemm_nn(
    const float* __restrict__ A, int lda, long long sA,
    const float* __restrict__ B, int ldb, long long sB,
    float* __restrict__ C, int ldc, long long sC,
    int M, int N, int K)
{
  __shared__ float As[16][68];
  __shared__ float Bs[16][68];
  int z = blockIdx.z;
  const float* Ab = A + (size_t)z*sA;
  const float* Bb = B + (size_t)z*sB;
  float* Cb = C + (size_t)z*sC;
  int m0 = blockIdx.y*64, n0 = blockIdx.x*64;
  int tid = threadIdx.x;
  int tx = tid & 15, ty = tid >> 4;
  float acc[4][4];
#pragma unroll
  for (int i=0;i<4;i++)
#pragma unroll
    for (int j=0;j<4;j++) acc[i][j]=0.f;

  int r = tid >> 2, c4 = (tid & 3)*4;
  int kr = tid >> 4, nc4 = (tid & 15)*4;

  for (int k0=0;k0<K;k0+=16){
    float4 va = make_float4(0.f,0.f,0.f,0.f);
    int m = m0 + r;
    if (m < M) va = *reinterpret_cast<const float4*>(Ab + (size_t)m*lda + k0 + c4);
    As[c4+0][r]=va.x; As[c4+1][r]=va.y; As[c4+2][r]=va.z; As[c4+3][r]=va.w;
    float4 vb = *reinterpret_cast<const float4*>(Bb + (size_t)(k0+kr)*ldb + n0 + nc4);
    Bs[kr][nc4+0]=vb.x; Bs[kr][nc4+1]=vb.y; Bs[kr][nc4+2]=vb.z; Bs[kr][nc4+3]=vb.w;
    __syncthreads();
#pragma unroll
    for (int kk=0;kk<16;kk++){
      float4 a = *reinterpret_cast<const float4*>(&As[kk][ty*4]);
      float4 b = *reinterpret_cast<const float4*>(&Bs[kk][tx*4]);
      acc[0][0]+=a.x*b.x; acc[0][1]+=a.x*b.y; acc[0][2]+=a.x*b.z; acc[0][3]+=a.x*b.w;
      acc[1][0]+=a.y*b.x; acc[1][1]+=a.y*b.y; acc[1][2]+=a.y*b.z; acc[1][3]+=a.y*b.w;
      acc[2][0]+=a.z*b.x; acc[2][1]+=a.z*b.y; acc[2][2]+=a.z*b.z; acc[2][3]+=a.z*b.w;
      acc[3][0]+=a.w*b.x; acc[3][1]+=a.w*b.y; acc[3][2]+=a.w*b.z; acc[3][3]+=a.w*b.w;
    }
    __syncthreads();
  }
#pragma unroll
  for (int i=0;i<4;i++){
    int m = m0 + ty*4 + i;
    if (m < M){
#pragma unroll
      for (int j=0;j<4;j++) Cb[(size_t)m*ldc + (n0 + tx*4 + j)] = acc[i][j];
    }
  }
}

// ------------- persistent wavefront recurrence (R7 core + quarter pipeline) -------------
__device__ __forceinline__ void gridbar(unsigned target){
  __threadfence();
  __syncthreads();
  if (threadIdx.x == 0){
    atomicAdd(&g_barc, 1u);
    while (*(volatile unsigned*)&g_barc < target) { }
  }
  __syncthreads();
}

// stage one K-quarter (16 batches x 256 floats = 16KB) with 512 threads
__device__ __forceinline__ void stage_q(const float* __restrict__ src, int kbase, float* buf){
  int tid = threadIdx.x;
#pragma unroll
  for (int i=0;i<2;i++){
    int idx = tid + (i<<9);              // 0..1023 float4s
    int b = idx >> 6, c = idx & 63;
    ((float4*)buf)[idx] = __ldcg((const float4*)(src + (b<<10) + kbase) + c);
  }
}

// dot over one K-quarter: warp = unit ju, 4 gate rows, batches [B0, B0+8)  (R7 mapping)
__device__ __forceinline__ void dot_q(const float* __restrict__ W, int kbase,
    const float* __restrict__ buf, int ju, int lane, int B0, ull (&acc)[4][8])
{
#pragma unroll
  for (int m=0;m<4;m++){
    int p2 = (lane + (m<<5)) << 1;       // float offset within quarter, 0..254
    ull wv[4];
#pragma unroll
    for (int r=0;r<4;r++)
      wv[r] = __ldcg((const ull*)(W + ((size_t)(ju + (r<<10)))*1024 + kbase + p2));
#pragma unroll
    for (int bb=0;bb<8;bb++){
      ull hv = *(const ull*)(buf + ((B0+bb)<<8) + p2);
#pragma unroll
      for (int r=0;r<4;r++) FMA2(acc[r][bb], wv[r], hv);
    }
  }
}

__device__ __forceinline__ void zacc(ull (&acc)[4][8]){
#pragma unroll
  for (int r=0;r<4;r++)
#pragma unroll
    for (int bb=0;bb<8;bb++) acc[r][bb] = 0ull;
}

// R7 reduce: 32 partials (index r*8+bb) -> lane L holds full sum of index L
__device__ __forceinline__ float reduce32(ull (&acc)[4][8], int lane){
  float v[32];
#pragma unroll
  for (int r=0;r<4;r++)
#pragma unroll
    for (int bb=0;bb<8;bb++){
      ull x = acc[r][bb];
      v[r*8+bb] = __uint_as_float((unsigned)x) + __uint_as_float((unsigned)(x>>32));
    }
#pragma unroll
  for (int off=16; off>=1; off>>=1){
#pragma unroll
    for (int i=0;i<16;i++){
      if (i < off){
        float a = (lane & off) ? v[i+off] : v[i];
        float b = (lane & off) ? v[i]     : v[i+off];
        v[i] = a + __shfl_xor_sync(0xffffffffu, b, off);
      }
    }
  }
  return v[0];
}

// R7-style epilogue; active==false skips state update/writes
__device__ __forceinline__ void lstm_epi(
    ull (&acc)[4][8], int lane, int ju, int B0, float bias,
    const float* x0p,      // per-lane pointer into g_X0 or nullptr
    float& c, float* hdst, float* hsdst, int t, bool active)
{
  int mybb = lane & 7;
  float g = reduce32(acc, lane) + bias;
  if (x0p) g += __ldcg(x0p);
  float gi = __shfl_sync(0xffffffffu, g, mybb);
  float gf = __shfl_sync(0xffffffffu, g, 8 + mybb);
  float gg = __shfl_sync(0xffffffffu, g, 16 + mybb);
  float go = __shfl_sync(0xffffffffu, g, 24 + mybb);
  if (active && lane < 8){
    float iv=sigm(gi), fv=sigm(gf), gv=tanhf(gg), ov=sigm(go);
    c = fv*c + iv*gv;
    float h = ov * tanhf(c);
    int b = B0 + lane;
    hdst[(b<<10) + ju] = h;
    if (hsdst) hsdst[((size_t)b*TSTEPS + t)*HSZ + ju] = h;
  }
}

__global__ void __launch_bounds__(512,1) k_recur(
    const float* __restrict__ Whh0, const float* __restrict__ bi0, const float* __restrict__ bh0,
    const float* __restrict__ Wih1, const float* __restrict__ Whh1,
    const float* __restrict__ bi1, const float* __restrict__ bh1,
    const float* __restrict__ Wih2, const float* __restrict__ Whh2,
    const float* __restrict__ bi2, const float* __restrict__ bh2)
{
  __shared__ __align__(16) float buf[2][BSZ*256];   // 2 x 16KB
  int tid = threadIdx.x, lane = tid & 31, wid = tid >> 5;
  int ju = blockIdx.x*8 + (wid >> 1);     // unit owned by this warp (R7 mapping)
  int B0 = (wid & 1) * 8;                 // batch half
  int myr = lane >> 3, mybb = lane & 7;

  float bias0, bias1, bias2;
  {
    int rr = (myr<<10) + ju;
    bias0 = bi0[rr] + bh0[rr];
    bias1 = bi1[rr] + bh1[rr];
    bias2 = bi2[rr] + bh2[rr];
  }

  float c0 = 0.f, c1 = 0.f, c2 = 0.f;    // cell state (lanes 0-7)
  ull acc[4][8];

  for (int p = 0; p < TSTEPS + 2; p++){
    int t0 = p, t1 = p - 1, t2 = p - 2;
    const float* S[5] = { g_h[0][(t0+1)&1], g_h[0][t1&1], g_h[1][(t1+1)&1],
                          g_h[1][t2&1],     g_h[2][(t2+1)&1] };
    const float* W[5] = { Whh0, Wih1, Whh1, Wih2, Whh2 };

    const float* x0p = (t0 < TSTEPS)
      ? &g_X0[((size_t)(t0*BSZ + B0 + mybb))*4096 + (myr<<10) + ju] : nullptr;

    stage_q(S[0], 0, buf[0]);
    __syncthreads();
    zacc(acc);
#pragma unroll
    for (int q = 0; q < 20; q++){
      if (q < 19) stage_q(S[(q+1)>>2], ((q+1)&3)<<8, buf[(q+1)&1]);
      dot_q(W[q>>2], (q&3)<<8, buf[q&1], ju, lane, B0, acc);
      if (q == 3){
        lstm_epi(acc, lane, ju, B0, bias0, x0p, c0, g_h[0][t0&1], nullptr, t0, t0 < TSTEPS);
        zacc(acc);
      } else if (q == 11){
        lstm_epi(acc, lane, ju, B0, bias1, nullptr, c1, g_h[1][t1&1], nullptr, t1,
                 (t1 >= 0) && (t1 < TSTEPS));
        zacc(acc);
      } else if (q == 19){
        lstm_epi(acc, lane, ju, B0, bias2, nullptr, c2, g_h[2][t2&1], g_hs, t2, t2 >= 0);
      }
      if (q < 19) __syncthreads();
    }
    gridbar((unsigned)(p+1) * NB);
  }
}

// ------------- softmax over S=512 -------------
__global__ void k_softmax(){
  int m = blockIdx.x;
  float* row = g_att + (size_t)m * SENC;
  int tid = threadIdx.x;            // 128
  __shared__ float sm[4];
  float v[4];
#pragma unroll
  for (int i=0;i<4;i++) v[i] = row[tid + 128*i];
  float mx = fmaxf(fmaxf(v[0],v[1]), fmaxf(v[2],v[3]));
#pragma unroll
  for (int o=16;o>0;o>>=1) mx = fmaxf(mx, __shfl_xor_sync(0xffffffffu, mx, o));
  if ((tid & 31) == 0) sm[tid>>5] = mx;
  __syncthreads();
  mx = fmaxf(fmaxf(sm[0],sm[1]), fmaxf(sm[2],sm[3]));
  float s = 0.f;
#pragma unroll
  for (int i=0;i<4;i++){ v[i] = expf(v[i]-mx); s += v[i]; }
#pragma unroll
  for (int o=16;o>0;o>>=1) s += __shfl_xor_sync(0xffffffffu, s, o);
  __syncthreads();
  if ((tid & 31) == 0) sm[tid>>5] = s;
  __syncthreads();
  s = sm[0]+sm[1]+sm[2]+sm[3];
  float inv = 1.f / s;
#pragma unroll
  for (int i=0;i<4;i++) row[tid + 128*i] = v[i]*inv;
}

// ------------- NLL over V=1024 -------------
__global__ void k_nll(){
  int m = blockIdx.x;
  const float* row = g_logits + (size_t)m * 1024;
  int tid = threadIdx.x;            // 256
  __shared__ float sm[8];
  float v[4];
#pragma unroll
  for (int i=0;i<4;i++) v[i] = row[tid + 256*i];
  float mx = fmaxf(fmaxf(v[0],v[1]), fmaxf(v[2],v[3]));
#pragma unroll
  for (int o=16;o>0;o>>=1) mx = fmaxf(mx, __shfl_xor_sync(0xffffffffu, mx, o));
  if ((tid & 31) == 0) sm[tid>>5] = mx;
  __syncthreads();
  mx = sm[0];
#pragma unroll
  for (int i=1;i<8;i++) mx = fmaxf(mx, sm[i]);
  float s = 0.f;
#pragma unroll
  for (int i=0;i<4;i++) s += expf(v[i]-mx);
#pragma unroll
  for (int o=16;o>0;o>>=1) s += __shfl_xor_sync(0xffffffffu, s, o);
  __syncthreads();
  if ((tid & 31) == 0) sm[tid>>5] = s;
  __syncthreads();
  if (tid == 0){
    float tot = 0.f;
#pragma unroll
    for (int i=0;i<8;i++) tot += sm[i];
    g_nll[m] = (logf(tot) + mx) - row[g_tgt[m]];
  }
}

__global__ void k_final(float* __restrict__ out){
  int tid = threadIdx.x;            // 256
  __shared__ float sm[8];
  float s = 0.f;
  for (int i=tid; i<MROWS; i+=256) s += g_nll[i];
#pragma unroll
  for (int o=16;o>0;o>>=1) s += __shfl_xor_sync(0xffffffffu, s, o);
  if ((tid & 31) == 0) sm[tid>>5] = s;
  __syncthreads();
  if (tid == 0){
    float tot = 0.f;
#pragma unroll
    for (int i=0;i<8;i++) tot += sm[i];
    out[0] = tot / (float)MROWS;
  }
}

// ------------- launcher -------------
extern "C" void kernel_launch(void* const* d_in, const int* in_sizes, int n_in,
                              void* d_out, int out_size)
{
  const int*   tokens = (const int*)  d_in[0];
  const float* enc    = (const float*)d_in[1];
  const float* emb    = (const float*)d_in[2];   // (1024, 512): E = 512
  const float* Wih0   = (const float*)d_in[3];   // (4096, 1536)
  const float* Whh0   = (const float*)d_in[4];
  const float* bi0    = (const float*)d_in[5];
  const float* bh0    = (const float*)d_in[6];
  const float* Wih1   = (const float*)d_in[7];
  const float* Whh1   = (const float*)d_in[8];
  const float* bi1    = (const float*)d_in[9];
  const float* bh1    = (const float*)d_in[10];
  const float* Wih2   = (const float*)d_in[11];
  const float* Whh2   = (const float*)d_in[12];
  const float* bi2    = (const float*)d_in[13];
  const float* bh2    = (const float*)d_in[14];
  const float* W1     = (const float*)d_in[15];
  const float* b1     = (const float*)d_in[16];
  const float* W2     = (const float*)d_in[17];
  const float* b2     = (const float*)d_in[18];
  float* out = (float*)d_out;

  void *pX0,*pHS,*pCTX,*pATT,*pHID,*pLOG;
  cudaGetSymbolAddress(&pX0,  g_X0);
  cudaGetSymbolAddress(&pHS,  g_hs);
  cudaGetSymbolAddress(&pCTX, g_ctx);
  cudaGetSymbolAddress(&pATT, g_att);
  cudaGetSymbolAddress(&pHID, g_hidden);
  cudaGetSymbolAddress(&pLOG, g_logits);
  float* X0 = (float*)pX0;

  k_init<<<384,256>>>(tokens);

  // X0[4112, 4096] = gather(emb)[.,512] @ W_ih0[:, :512]^T (lda=512, ldb=1536, K=512)
  k_gemm_nt<<<dim3(64,65,1),256>>>(emb,ESZ,0, nullptr,ESZ,1<<30, 1,
                                   Wih0,1536,0, X0, 4096,0,
                                   MROWS,4096,ESZ, nullptr,0);

  k_recur<<<NB,512>>>(Whh0,bi0,bh0, Wih1,Whh1,bi1,bh1, Wih2,Whh2,bi2,bh2);

  // scores[b]: hs[b] (257x1024) @ enc[b]^T (512x1024)
  k_gemm_nt<<<dim3(8,5,16),256>>>((const float*)pHS,1024,257LL*1024, nullptr,1024,1<<30, 0,
                                  enc,1024,512LL*1024, (float*)pATT,512,257LL*512,
                                  257,512,1024, nullptr,0);

  k_softmax<<<MROWS,128>>>();

  // ctx[b]: attn[b] (257x512) @ enc[b] (512x1024)
  k_gemm_nn<<<dim3(16,5,16),256>>>((const float*)pATT,512,257LL*512,
                                   enc,1024,512LL*1024,
                                   (float*)pCTX,1024,257LL*1024, 257,1024,512);

  // hidden = tanh([hs|ctx] @ W1^T + b1)
  k_gemm_nt<<<dim3(16,65,1),256>>>((const float*)pHS,1024,0, (const float*)pCTX,1024,1024, 0,
                                   W1,2048,0, (float*)pHID,1024,0,
                                   MROWS,1024,2048, b1,1);

  // logits = hidden @ W2^T + b2
  k_gemm_nt<<<dim3(16,65,1),256>>>((const float*)pHID,1024,0, nullptr,1024,1<<30, 0,
                                   W2,1024,0, (float*)pLOG,1024,0,
                                   MROWS,1024,1024, b2,0);

  k_nll<<<MROWS,256>>>();
  k_final<<<1,256>>>(out);
}

// round 10
// speedup vs baseline: 2.2861x; 1.0627x over previous
#include <cuda_runtime.h>
#include <cstdint>
#include <cstddef>

#define HSZ 1024
#define BSZ 16
#define TSTEPS 257
#define SENC 512
#define ESZ 512
#define MROWS (BSZ*TSTEPS)
#define NB 128
typedef unsigned long long ull;

// ------------- device scratch (statics; no allocations) -------------
__device__ float g_X0[(size_t)MROWS * 4096];      // [t*16+b][gate_row] row-major
__device__ float g_hs[(size_t)MROWS * HSZ];       // [b*257+t][j]
__device__ float g_ctx[(size_t)MROWS * HSZ];
__device__ float g_att[(size_t)MROWS * SENC];
__device__ float g_hidden[(size_t)MROWS * HSZ];
__device__ float g_logits[(size_t)MROWS * HSZ];   // V==1024
__device__ float g_h[3][2][BSZ * HSZ];            // ping-pong hidden per layer
__device__ float g_nll[MROWS];
__device__ int   g_tok[MROWS];                    // dec_in, index t*16+b
__device__ int   g_tgt[MROWS];                    // dec_out, index b*257+t
__device__ unsigned g_barc;

#define FMA2(a,x,y) asm("fma.rn.f32x2 %0, %1, %2, %0;" : "+l"(a) : "l"(x), "l"(y))
#define PACK2(o,f)  asm("mov.b64 %0, {%1, %1};" : "=l"(o) : "r"(__float_as_uint(f)))
__device__ __forceinline__ float sigm(float x){ return 1.f/(1.f+expf(-x)); }

// ------------- init -------------
__global__ void k_init(const int* __restrict__ tokens){
  int i = blockIdx.x*blockDim.x + threadIdx.x;
  if (i == 0) g_barc = 0u;
  if (i < 3*2*BSZ*HSZ) ((float*)g_h)[i] = 0.f;
  if (i < MROWS){
    int t = i / BSZ, b = i % BSZ;
    g_tok[i] = (t == 0) ? 1 : tokens[b*256 + (t-1)];
    int b2 = i / TSTEPS, t2 = i % TSTEPS;
    g_tgt[i] = (t2 < 256) ? tokens[b2*256 + t2] : 2;
  }
}

// ------------- NT GEMM 128x128: C = A(MxK) * B(NxK)^T, options -------------
// 256 threads, 8x8 per thread, FMA2 (packed fp32). N must be a multiple of 128.
__global__ void __launch_bounds__(256) k_gemm_nt(
    const float* __restrict__ A, int lda, long long sA,
    const float* __restrict__ A2, int lda2, int ksplit, int gather,
    const float* __restrict__ B, int ldb, long long sB,
    float* __restrict__ C, int ldc, long long sC,
    int M, int N, int K, const float* __restrict__ bias, int act)
{
  __shared__ __align__(16) float As[16][132];
  __shared__ __align__(16) float Bs[16][132];
  int z = blockIdx.z;
  const float* Ab = A + (size_t)z * sA;
  const float* Bb = B + (size_t)z * sB;
  float* Cb = C + (size_t)z * sC;
  int m0 = blockIdx.y*128, n0 = blockIdx.x*128;
  int tid = threadIdx.x;
  int tx = tid & 15, ty = tid >> 4;

  ull acc[8][4];
#pragma unroll
  for (int i=0;i<8;i++)
#pragma unroll
    for (int j=0;j<4;j++) acc[i][j] = 0ull;

  for (int k0 = 0; k0 < K; k0 += 16){
#pragma unroll
    for (int i=0;i<2;i++){
      int f = tid + (i<<8);
      int row = f >> 2, c4 = (f & 3) * 4;
      // A tile
      float4 va = make_float4(0.f,0.f,0.f,0.f);
      int m = m0 + row;
      if (m < M){
        int kg = k0 + c4;
        int arow = gather ? g_tok[m] : m;
        const float* src;
        if (A2 && kg >= ksplit) src = A2 + (size_t)arow*lda2 + (kg - ksplit);
        else                    src = Ab + (size_t)arow*lda + kg;
        va = *reinterpret_cast<const float4*>(src);
      }
      As[c4+0][row]=va.x; As[c4+1][row]=va.y; As[c4+2][row]=va.z; As[c4+3][row]=va.w;
      // B tile (N multiple of 128 -> always in range)
      float4 vb = *reinterpret_cast<const float4*>(Bb + (size_t)(n0+row)*ldb + k0 + c4);
      Bs[c4+0][row]=vb.x; Bs[c4+1][row]=vb.y; Bs[c4+2][row]=vb.z; Bs[c4+3][row]=vb.w;
    }
    __syncthreads();
#pragma unroll
    for (int kk=0;kk<16;kk++){
      float4 a0 = *reinterpret_cast<const float4*>(&As[kk][ty*8]);
      float4 a1 = *reinterpret_cast<const float4*>(&As[kk][ty*8+4]);
      ulonglong2 b0 = *reinterpret_cast<const ulonglong2*>(&Bs[kk][tx*8]);
      ulonglong2 b1 = *reinterpret_cast<const ulonglong2*>(&Bs[kk][tx*8+4]);
      float af[8] = {a0.x,a0.y,a0.z,a0.w,a1.x,a1.y,a1.z,a1.w};
#pragma unroll
      for (int i=0;i<8;i++){
        ull aa; PACK2(aa, af[i]);
        FMA2(acc[i][0], aa, b0.x);
        FMA2(acc[i][1], aa, b0.y);
        FMA2(acc[i][2], aa, b1.x);
        FMA2(acc[i][3], aa, b1.y);
      }
    }
    __syncthreads();
  }
#pragma unroll
  for (int i=0;i<8;i++){
    int m = m0 + ty*8 + i;
    if (m < M){
#pragma unroll
      for (int j=0;j<4;j++){
        int n = n0 + tx*8 + j*2;
        ull v = acc[i][j];
        float lo = __uint_as_float((unsigned)v);
        float hi = __uint_as_float((unsigned)(v>>32));
        if (bias){ lo += bias[n]; hi += bias[n+1]; }
        if (act){ lo = tanhf(lo); hi = tanhf(hi); }
        *reinterpret_cast<float2*>(&Cb[(size_t)m*ldc + n]) = make_float2(lo, hi);
      }
    }
  }
}

// ------------- NN GEMM: C = A(MxK) * B(KxN) (unchanged, ctx only) -------------
__global__ void __launch_bounds__(256) k_gemm_nn(
    const float* __restrict__ A, int lda, long long sA,
    const float* __restrict__ B, int ldb, long long sB,
    float* __restrict__ C, int ldc, long long sC,
    int M, int N, int K)
{
  __shared__ float As[16][68];
  __shared__ float Bs[16][68];
  int z = blockIdx.z;
  const float* Ab = A + (size_t)z*sA;
  const float* Bb = B + (size_t)z*sB;
  float* Cb = C + (size_t)z*sC;
  int m0 = blockIdx.y*64, n0 = blockIdx.x*64;
  int tid = threadIdx.x;
  int tx = tid & 15, ty = tid >> 4;
  float acc[4][4];
#pragma unroll
  for (int i=0;i<4;i++)
#pragma unroll
    for (int j=0;j<4;j++) acc[i][j]=0.f;

  int r = tid >> 2, c4 = (tid & 3)*4;
  int kr = tid >> 4, nc4 = (tid & 15)*4;

  for (int k0=0;k0<K;k0+=16){
    float4 va = make_float4(0.f,0.f,0.f,0.f);
    int m = m0 + r;
    if (m < M) va = *reinterpret_cast<const float4*>(Ab + (size_t)m*lda + k0 + c4);
    As[c4+0][r]=va.x; As[c4+1][r]=va.y; As[c4+2][r]=va.z; As[c4+3][r]=va.w;
    float4 vb = *reinterpret_cast<const float4*>(Bb + (size_t)(k0+kr)*ldb + n0 + nc4);
    Bs[kr][nc4+0]=vb.x; Bs[kr][nc4+1]=vb.y; Bs[kr][nc4+2]=vb.z; Bs[kr][nc4+3]=vb.w;
    __syncthreads();
#pragma unroll
    for (int kk=0;kk<16;kk++){
      float4 a = *reinterpret_cast<const float4*>(&As[kk][ty*4]);
      float4 b = *reinterpret_cast<const float4*>(&Bs[kk][tx*4]);
      acc[0][0]+=a.x*b.x; acc[0][1]+=a.x*b.y; acc[0][2]+=a.x*b.z; acc[0][3]+=a.x*b.w;
      acc[1][0]+=a.y*b.x; acc[1][1]+=a.y*b.y; acc[1][2]+=a.y*b.z; acc[1][3]+=a.y*b.w;
      acc[2][0]+=a.z*b.x; acc[2][1]+=a.z*b.y; acc[2][2]+=a.z*b.z; acc[2][3]+=a.z*b.w;
      acc[3][0]+=a.w*b.x; acc[3][1]+=a.w*b.y; acc[3][2]+=a.w*b.z; acc[3][3]+=a.w*b.w;
    }
    __syncthreads();
  }
#pragma unroll
  for (int i=0;i<4;i++){
    int m = m0 + ty*4 + i;
    if (m < M){
#pragma unroll
      for (int j=0;j<4;j++) Cb[(size_t)m*ldc + (n0 + tx*4 + j)] = acc[i][j];
    }
  }
}

// ------------- persistent wavefront recurrence (R9 core, vectorized dot) -------------
__device__ __forceinline__ void gridbar(unsigned target){
  __threadfence();
  __syncthreads();
  if (threadIdx.x == 0){
    atomicAdd(&g_barc, 1u);
    while (*(volatile unsigned*)&g_barc < target) { __nanosleep(64); }
  }
  __syncthreads();
}

// stage one K-quarter (16 batches x 256 floats = 16KB) with 512 threads
__device__ __forceinline__ void stage_q(const float* __restrict__ src, int kbase, float* buf){
  int tid = threadIdx.x;
#pragma unroll
  for (int i=0;i<2;i++){
    int idx = tid + (i<<9);              // 0..1023 float4s
    int b = idx >> 6, c = idx & 63;
    ((float4*)buf)[idx] = __ldcg((const float4*)(src + (b<<10) + kbase) + c);
  }
}

// dot over one K-quarter: warp = unit ju, 4 gate rows, batches [B0, B0+8)
// 16B vector loads for both W (LDG.128) and h (LDS.128)
__device__ __forceinline__ void dot_q(const float* __restrict__ W, int kbase,
    const float* __restrict__ buf, int ju, int lane, int B0, ull (&acc)[4][8])
{
#pragma unroll
  for (int m=0;m<2;m++){
    int kq = (lane<<2) + (m<<7);         // float offset within quarter, 0..252, 16B aligned
    ulonglong2 wv[4];
#pragma unroll
    for (int r=0;r<4;r++)
      wv[r] = __ldcg((const ulonglong2*)(W + ((size_t)(ju + (r<<10)))*1024 + kbase + kq));
#pragma unroll
    for (int bb=0;bb<8;bb++){
      ulonglong2 hv = *(const ulonglong2*)(buf + ((B0+bb)<<8) + kq);
#pragma unroll
      for (int r=0;r<4;r++){
        FMA2(acc[r][bb], wv[r].x, hv.x);
        FMA2(acc[r][bb], wv[r].y, hv.y);
      }
    }
  }
}

__device__ __forceinline__ void zacc(ull (&acc)[4][8]){
#pragma unroll
  for (int r=0;r<4;r++)
#pragma unroll
    for (int bb=0;bb<8;bb++) acc[r][bb] = 0ull;
}

// reduce 32 partials (index r*8+bb) -> lane L holds full sum of index L
__device__ __forceinline__ float reduce32(ull (&acc)[4][8], int lane){
  float v[32];
#pragma unroll
  for (int r=0;r<4;r++)
#pragma unroll
    for (int bb=0;bb<8;bb++){
      ull x = acc[r][bb];
      v[r*8+bb] = __uint_as_float((unsigned)x) + __uint_as_float((unsigned)(x>>32));
    }
#pragma unroll
  for (int off=16; off>=1; off>>=1){
#pragma unroll
    for (int i=0;i<16;i++){
      if (i < off){
        float a = (lane & off) ? v[i+off] : v[i];
        float b = (lane & off) ? v[i]     : v[i+off];
        v[i] = a + __shfl_xor_sync(0xffffffffu, b, off);
      }
    }
  }
  return v[0];
}

// epilogue for one layer; active==false skips state update/writes
__device__ __forceinline__ void lstm_epi(
    ull (&acc)[4][8], int lane, int ju, int B0, float bias,
    const float* x0p,      // per-lane pointer into g_X0 or nullptr
    float& c, float* hdst, float* hsdst, int t, bool active)
{
  int mybb = lane & 7;
  float g = reduce32(acc, lane) + bias;
  if (x0p) g += __ldcg(x0p);
  float gi = __shfl_sync(0xffffffffu, g, mybb);
  float gf = __shfl_sync(0xffffffffu, g, 8 + mybb);
  float gg = __shfl_sync(0xffffffffu, g, 16 + mybb);
  float go = __shfl_sync(0xffffffffu, g, 24 + mybb);
  if (active && lane < 8){
    float iv=sigm(gi), fv=sigm(gf), gv=tanhf(gg), ov=sigm(go);
    c = fv*c + iv*gv;
    float h = ov * tanhf(c);
    int b = B0 + lane;
    hdst[(b<<10) + ju] = h;
    if (hsdst) hsdst[((size_t)b*TSTEPS + t)*HSZ + ju] = h;
  }
}

__global__ void __launch_bounds__(512,1) k_recur(
    const float* __restrict__ Whh0, const float* __restrict__ bi0, const float* __restrict__ bh0,
    const float* __restrict__ Wih1, const float* __restrict__ Whh1,
    const float* __restrict__ bi1, const float* __restrict__ bh1,
    const float* __restrict__ Wih2, const float* __restrict__ Whh2,
    const float* __restrict__ bi2, const float* __restrict__ bh2)
{
  __shared__ __align__(16) float buf[2][BSZ*256];   // 2 x 16KB
  int tid = threadIdx.x, lane = tid & 31, wid = tid >> 5;
  int ju = blockIdx.x*8 + (wid >> 1);     // unit owned by this warp
  int B0 = (wid & 1) * 8;                 // batch half
  int myr = lane >> 3, mybb = lane & 7;

  float bias0, bias1, bias2;
  {
    int rr = (myr<<10) + ju;
    bias0 = bi0[rr] + bh0[rr];
    bias1 = bi1[rr] + bh1[rr];
    bias2 = bi2[rr] + bh2[rr];
  }

  float c0 = 0.f, c1 = 0.f, c2 = 0.f;    // cell state (lanes 0-7)
  ull acc[4][8];

  for (int p = 0; p < TSTEPS + 2; p++){
    int t0 = p, t1 = p - 1, t2 = p - 2;
    const float* S[5] = { g_h[0][(t0+1)&1], g_h[0][t1&1], g_h[1][(t1+1)&1],
                          g_h[1][t2&1],     g_h[2][(t2+1)&1] };
    const float* W[5] = { Whh0, Wih1, Whh1, Wih2, Whh2 };

    const float* x0p = (t0 < TSTEPS)
      ? &g_X0[((size_t)(t0*BSZ + B0 + mybb))*4096 + (myr<<10) + ju] : nullptr;

    stage_q(S[0], 0, buf[0]);
    __syncthreads();
    zacc(acc);
#pragma unroll
    for (int q = 0; q < 20; q++){
      if (q < 19) stage_q(S[(q+1)>>2], ((q+1)&3)<<8, buf[(q+1)&1]);
      dot_q(W[q>>2], (q&3)<<8, buf[q&1], ju, lane, B0, acc);
      if (q == 3){
        lstm_epi(acc, lane, ju, B0, bias0, x0p, c0, g_h[0][t0&1], nullptr, t0, t0 < TSTEPS);
        zacc(acc);
      } else if (q == 11){
        lstm_epi(acc, lane, ju, B0, bias1, nullptr, c1, g_h[1][t1&1], nullptr, t1,
                 (t1 >= 0) && (t1 < TSTEPS));
        zacc(acc);
      } else if (q == 19){
        lstm_epi(acc, lane, ju, B0, bias2, nullptr, c2, g_h[2][t2&1], g_hs, t2, t2 >= 0);
      }
      if (q < 19) __syncthreads();
    }
    gridbar((unsigned)(p+1) * NB);
  }
}

// ------------- softmax over S=512 -------------
__global__ void k_softmax(){
  int m = blockIdx.x;
  float* row = g_att + (size_t)m * SENC;
  int tid = threadIdx.x;            // 128
  __shared__ float sm[4];
  float v[4];
#pragma unroll
  for (int i=0;i<4;i++) v[i] = row[tid + 128*i];
  float mx = fmaxf(fmaxf(v[0],v[1]), fmaxf(v[2],v[3]));
#pragma unroll
  for (int o=16;o>0;o>>=1) mx = fmaxf(mx, __shfl_xor_sync(0xffffffffu, mx, o));
  if ((tid & 31) == 0) sm[tid>>5] = mx;
  __syncthreads();
  mx = fmaxf(fmaxf(sm[0],sm[1]), fmaxf(sm[2],sm[3]));
  float s = 0.f;
#pragma unroll
  for (int i=0;i<4;i++){ v[i] = expf(v[i]-mx); s += v[i]; }
#pragma unroll
  for (int o=16;o>0;o>>=1) s += __shfl_xor_sync(0xffffffffu, s, o);
  __syncthreads();
  if ((tid & 31) == 0) sm[tid>>5] = s;
  __syncthreads();
  s = sm[0]+sm[1]+sm[2]+sm[3];
  float inv = 1.f / s;
#pragma unroll
  for (int i=0;i<4;i++) row[tid + 128*i] = v[i]*inv;
}

// ------------- NLL over V=1024 -------------
__global__ void k_nll(){
  int m = blockIdx.x;
  const float* row = g_logits + (size_t)m * 1024;
  int tid = threadIdx.x;            // 256
  __shared__ float sm[8];
  float v[4];
#pragma unroll
  for (int i=0;i<4;i++) v[i] = row[tid + 256*i];
  float mx = fmaxf(fmaxf(v[0],v[1]), fmaxf(v[2],v[3]));
#pragma unroll
  for (int o=16;o>0;o>>=1) mx = fmaxf(mx, __shfl_xor_sync(0xffffffffu, mx, o));
  if ((tid & 31) == 0) sm[tid>>5] = mx;
  __syncthreads();
  mx = sm[0];
#pragma unroll
  for (int i=1;i<8;i++) mx = fmaxf(mx, sm[i]);
  float s = 0.f;
#pragma unroll
  for (int i=0;i<4;i++) s += expf(v[i]-mx);
#pragma unroll
  for (int o=16;o>0;o>>=1) s += __shfl_xor_sync(0xffffffffu, s, o);
  __syncthreads();
  if ((tid & 31) == 0) sm[tid>>5] = s;
  __syncthreads();
  if (tid == 0){
    float tot = 0.f;
#pragma unroll
    for (int i=0;i<8;i++) tot += sm[i];
    g_nll[m] = (logf(tot) + mx) - row[g_tgt[m]];
  }
}

__global__ void k_final(float* __restrict__ out){
  int tid = threadIdx.x;            // 256
  __shared__ float sm[8];
  float s = 0.f;
  for (int i=tid; i<MROWS; i+=256) s += g_nll[i];
#pragma unroll
  for (int o=16;o>0;o>>=1) s += __shfl_xor_sync(0xffffffffu, s, o);
  if ((tid & 31) == 0) sm[tid>>5] = s;
  __syncthreads();
  if (tid == 0){
    float tot = 0.f;
#pragma unroll
    for (int i=0;i<8;i++) tot += sm[i];
    out[0] = tot / (float)MROWS;
  }
}

// ------------- launcher -------------
extern "C" void kernel_launch(void* const* d_in, const int* in_sizes, int n_in,
                              void* d_out, int out_size)
{
  const int*   tokens = (const int*)  d_in[0];
  const float* enc    = (const float*)d_in[1];
  const float* emb    = (const float*)d_in[2];   // (1024, 512): E = 512
  const float* Wih0   = (const float*)d_in[3];   // (4096, 1536)
  const float* Whh0   = (const float*)d_in[4];
  const float* bi0    = (const float*)d_in[5];
  const float* bh0    = (const float*)d_in[6];
  const float* Wih1   = (const float*)d_in[7];
  const float* Whh1   = (const float*)d_in[8];
  const float* bi1    = (const float*)d_in[9];
  const float* bh1    = (const float*)d_in[10];
  const float* Wih2   = (const float*)d_in[11];
  const float* Whh2   = (const float*)d_in[12];
  const float* bi2    = (const float*)d_in[13];
  const float* bh2    = (const float*)d_in[14];
  const float* W1     = (const float*)d_in[15];
  const float* b1     = (const float*)d_in[16];
  const float* W2     = (const float*)d_in[17];
  const float* b2     = (const float*)d_in[18];
  float* out = (float*)d_out;

  void *pX0,*pHS,*pCTX,*pATT,*pHID,*pLOG;
  cudaGetSymbolAddress(&pX0,  g_X0);
  cudaGetSymbolAddress(&pHS,  g_hs);
  cudaGetSymbolAddress(&pCTX, g_ctx);
  cudaGetSymbolAddress(&pATT, g_att);
  cudaGetSymbolAddress(&pHID, g_hidden);
  cudaGetSymbolAddress(&pLOG, g_logits);
  float* X0 = (float*)pX0;

  k_init<<<384,256>>>(tokens);

  // X0[4112, 4096] = gather(emb)[.,512] @ W_ih0[:, :512]^T (lda=512, ldb=1536, K=512)
  k_gemm_nt<<<dim3(32,33,1),256>>>(emb,ESZ,0, nullptr,ESZ,1<<30, 1,
                                   Wih0,1536,0, X0, 4096,0,
                                   MROWS,4096,ESZ, nullptr,0);

  k_recur<<<NB,512>>>(Whh0,bi0,bh0, Wih1,Whh1,bi1,bh1, Wih2,Whh2,bi2,bh2);

  // scores[b]: hs[b] (257x1024) @ enc[b]^T (512x1024)
  k_gemm_nt<<<dim3(4,3,16),256>>>((const float*)pHS,1024,257LL*1024, nullptr,1024,1<<30, 0,
                                  enc,1024,512LL*1024, (float*)pATT,512,257LL*512,
                                  257,512,1024, nullptr,0);

  k_softmax<<<MROWS,128>>>();

  // ctx[b]: attn[b] (257x512) @ enc[b] (512x1024)
  k_gemm_nn<<<dim3(16,5,16),256>>>((const float*)pATT,512,257LL*512,
                                   enc,1024,512LL*1024,
                                   (float*)pCTX,1024,257LL*1024, 257,1024,512);

  // hidden = tanh([hs|ctx] @ W1^T + b1)
  k_gemm_nt<<<dim3(8,33,1),256>>>((const float*)pHS,1024,0, (const float*)pCTX,1024,1024, 0,
                                  W1,2048,0, (float*)pHID,1024,0,
                                  MROWS,1024,2048, b1,1);

  // logits = hidden @ W2^T + b2
  k_gemm_nt<<<dim3(8,33,1),256>>>((const float*)pHID,1024,0, nullptr,1024,1<<30, 0,
                                  W2,1024,0, (float*)pLOG,1024,0,
                                  MROWS,1024,1024, b2,0);

  k_nll<<<MROWS,256>>>();
  k_final<<<1,256>>>(out);
}

// round 13
// speedup vs baseline: 2.4424x; 1.0684x over previous
#include <cuda_runtime.h>
#include <cuda_bf16.h>
#include <cstdint>
#include <cstddef>

#define HSZ 1024
#define BSZ 16
#define TSTEPS 257
#define SENC 512
#define ESZ 512
#define MROWS (BSZ*TSTEPS)
#define NB 128
typedef unsigned long long ull;

// ------------- device scratch (statics; no allocations) -------------
__device__ float g_X0[(size_t)MROWS * 4096];      // [t*16+b][gate_row] row-major
__device__ float g_hs[(size_t)MROWS * HSZ];       // [b*257+t][j]
__device__ float g_ctx[(size_t)MROWS * HSZ];
__device__ float g_att[(size_t)MROWS * SENC];
__device__ float g_logits[(size_t)MROWS * HSZ];   // V==1024
__device__ float g_h[3][2][BSZ * HSZ];            // ping-pong hidden per layer
__device__ float g_nll[MROWS];
__device__ int   g_tok[MROWS];                    // dec_in, index t*16+b
__device__ int   g_tgt[MROWS];                    // dec_out, index b*257+t
__device__ unsigned g_barc;
// bf16 operand mirrors for tensor-core tail
__device__ __nv_bfloat16 g_hsb[(size_t)MROWS * HSZ];
__device__ __nv_bfloat16 g_ctxb[(size_t)MROWS * HSZ];
__device__ __nv_bfloat16 g_hidb[(size_t)MROWS * HSZ];
__device__ __nv_bfloat16 g_encb[(size_t)BSZ * SENC * HSZ];
__device__ __nv_bfloat16 g_W1b[(size_t)HSZ * 2048];
__device__ __nv_bfloat16 g_W2b[(size_t)HSZ * HSZ];

#define FMA2(a,x,y) asm("fma.rn.f32x2 %0, %1, %2, %0;" : "+l"(a) : "l"(x), "l"(y))
#define PACK2(o,f)  asm("mov.b64 %0, {%1, %1};" : "=l"(o) : "r"(__float_as_uint(f)))
__device__ __forceinline__ float sigm(float x){ return 1.f/(1.f+expf(-x)); }

__device__ __forceinline__ uint32_t smem_u32(const void* p){
  uint32_t a;
  asm("{ .reg .u64 t; cvta.to.shared.u64 t, %1; cvt.u32.u64 %0, t; }" : "=r"(a) : "l"(p));
  return a;
}

// ------------- init -------------
__global__ void k_init(const int* __restrict__ tokens){
  int i = blockIdx.x*blockDim.x + threadIdx.x;
  if (i == 0) g_barc = 0u;
  if (i < 3*2*BSZ*HSZ) ((float*)g_h)[i] = 0.f;
  if (i < MROWS){
    int t = i / BSZ, b = i % BSZ;
    g_tok[i] = (t == 0) ? 1 : tokens[b*256 + (t-1)];
    int b2 = i / TSTEPS, t2 = i % TSTEPS;
    g_tgt[i] = (t2 < 256) ? tokens[b2*256 + t2] : 2;
  }
}

// fp32 -> bf16 convert
__global__ void k_cvt(const float* __restrict__ src, __nv_bfloat16* __restrict__ dst, int n){
  int i = blockIdx.x*blockDim.x + threadIdx.x;
  if (i < n) dst[i] = __float2bfloat16(src[i]);
}

// ------------- NT GEMM 128x128 fp32 (X0 only) -------------
__global__ void __launch_bounds__(256) k_gemm_nt(
    const float* __restrict__ A, int lda, long long sA,
    const float* __restrict__ A2, int lda2, int ksplit, int gather,
    const float* __restrict__ B, int ldb, long long sB,
    float* __restrict__ C, int ldc, long long sC,
    int M, int N, int K, const float* __restrict__ bias, int act)
{
  __shared__ __align__(16) float As[16][132];
  __shared__ __align__(16) float Bs[16][132];
  int z = blockIdx.z;
  const float* Ab = A + (size_t)z * sA;
  const float* Bb = B + (size_t)z * sB;
  float* Cb = C + (size_t)z * sC;
  int m0 = blockIdx.y*128, n0 = blockIdx.x*128;
  int tid = threadIdx.x;
  int tx = tid & 15, ty = tid >> 4;

  ull acc[8][4];
#pragma unroll
  for (int i=0;i<8;i++)
#pragma unroll
    for (int j=0;j<4;j++) acc[i][j] = 0ull;

  for (int k0 = 0; k0 < K; k0 += 16){
#pragma unroll
    for (int i=0;i<2;i++){
      int f = tid + (i<<8);
      int row = f >> 2, c4 = (f & 3) * 4;
      float4 va = make_float4(0.f,0.f,0.f,0.f);
      int m = m0 + row;
      if (m < M){
        int kg = k0 + c4;
        int arow = gather ? g_tok[m] : m;
        const float* src;
        if (A2 && kg >= ksplit) src = A2 + (size_t)arow*lda2 + (kg - ksplit);
        else                    src = Ab + (size_t)arow*lda + kg;
        va = *reinterpret_cast<const float4*>(src);
      }
      As[c4+0][row]=va.x; As[c4+1][row]=va.y; As[c4+2][row]=va.z; As[c4+3][row]=va.w;
      float4 vb = *reinterpret_cast<const float4*>(Bb + (size_t)(n0+row)*ldb + k0 + c4);
      Bs[c4+0][row]=vb.x; Bs[c4+1][row]=vb.y; Bs[c4+2][row]=vb.z; Bs[c4+3][row]=vb.w;
    }
    __syncthreads();
#pragma unroll
    for (int kk=0;kk<16;kk++){
      float4 a0 = *reinterpret_cast<const float4*>(&As[kk][ty*8]);
      float4 a1 = *reinterpret_cast<const float4*>(&As[kk][ty*8+4]);
      ulonglong2 b0 = *reinterpret_cast<const ulonglong2*>(&Bs[kk][tx*8]);
      ulonglong2 b1 = *reinterpret_cast<const ulonglong2*>(&Bs[kk][tx*8+4]);
      float af[8] = {a0.x,a0.y,a0.z,a0.w,a1.x,a1.y,a1.z,a1.w};
#pragma unroll
      for (int i=0;i<8;i++){
        ull aa; PACK2(aa, af[i]);
        FMA2(acc[i][0], aa, b0.x);
        FMA2(acc[i][1], aa, b0.y);
        FMA2(acc[i][2], aa, b1.x);
        FMA2(acc[i][3], aa, b1.y);
      }
    }
    __syncthreads();
  }
#pragma unroll
  for (int i=0;i<8;i++){
    int m = m0 + ty*8 + i;
    if (m < M){
#pragma unroll
      for (int j=0;j<4;j++){
        int n = n0 + tx*8 + j*2;
        ull v = acc[i][j];
        float lo = __uint_as_float((unsigned)v);
        float hi = __uint_as_float((unsigned)(v>>32));
        if (bias){ lo += bias[n]; hi += bias[n+1]; }
        if (act){ lo = tanhf(lo); hi = tanhf(hi); }
        *reinterpret_cast<float2*>(&Cb[(size_t)m*ldc + n]) = make_float2(lo, hi);
      }
    }
  }
}

// ------------- HMMA bf16 NT GEMM: C[M,N] = A(MxK) * B(NxK)^T -------------
// mma.sync m16n8k16, tile 128x64 per block (8 warps = 4M x 2N, warp 32x32).
// K multiple of 64; N multiple of 64. bf16 in, fp32 accumulate.
#define LDM4(r0,r1,r2,r3,ad) \
  asm volatile("ldmatrix.sync.aligned.m8n8.x4.shared.b16 {%0,%1,%2,%3}, [%4];" \
    : "=r"(r0),"=r"(r1),"=r"(r2),"=r"(r3) : "r"(ad))
#define MMA16816(c,a,b) \
  asm volatile("mma.sync.aligned.m16n8k16.row.col.f32.bf16.bf16.f32 " \
    "{%0,%1,%2,%3}, {%4,%5,%6,%7}, {%8,%9}, {%0,%1,%2,%3};" \
    : "+f"(c[0]),"+f"(c[1]),"+f"(c[2]),"+f"(c[3]) \
    : "r"(a[0]),"r"(a[1]),"r"(a[2]),"r"(a[3]), "r"(b[0]),"r"(b[1]))

__global__ void __launch_bounds__(256) k_gemm_tc(
    const __nv_bfloat16* __restrict__ A, int lda, long long sA,
    const __nv_bfloat16* __restrict__ A2, int lda2, int ksplit,
    const __nv_bfloat16* __restrict__ B, int ldb, long long sB,
    float* __restrict__ C, int ldc, long long sC,
    __nv_bfloat16* __restrict__ Cbf,
    int M, int N, int K, const float* __restrict__ bias, int act)
{
  __shared__ __align__(16) __nv_bfloat16 As[128][72];  // 64 data + 8 pad
  __shared__ __align__(16) __nv_bfloat16 Bs[64][72];
  int z = blockIdx.z;
  const __nv_bfloat16* Ab = A + (size_t)z * sA;
  const __nv_bfloat16* Bb = B + (size_t)z * sB;
  float* Cb = C ? C + (size_t)z * sC : nullptr;
  __nv_bfloat16* Cbb = Cbf ? Cbf + (size_t)z * sC : nullptr;
  int m0 = blockIdx.y*128, n0 = blockIdx.x*64;
  int tid = threadIdx.x, wid = tid >> 5, lane = tid & 31;
  int wm = wid >> 1, wn = wid & 1;           // warp tile: rows wm*32, cols wn*32
  int mb = wm*32, nb = wn*32;

  float acc[2][4][4];
#pragma unroll
  for (int h=0;h<2;h++)
#pragma unroll
    for (int f=0;f<4;f++)
#pragma unroll
      for (int e=0;e<4;e++) acc[h][f][e] = 0.f;

  // ldmatrix lane -> smem row/col-offset mapping (x4: quad q = lane/8)
  int q = lane >> 3, l8 = lane & 7;
  int a_row = l8 + (q & 1)*8, a_kof = (q >> 1)*8;       // A: m8x2 stack, k8x2
  int b_row = l8 + (q >> 1)*8, b_kof = (q & 1)*8;       // B: n8(lo k), n8(hi k) order

  for (int k0 = 0; k0 < K; k0 += 64){
    const __nv_bfloat16* Asrc; int kc, ldx;
    if (A2 && k0 >= ksplit){ Asrc = A2; kc = k0 - ksplit; ldx = lda2; }
    else                   { Asrc = Ab; kc = k0;          ldx = lda;  }
    // stage A: 128 rows x 64 bf16 (8x uint4 per row)
#pragma unroll
    for (int i=0;i<4;i++){
      int u = tid + (i<<8);
      int row = u >> 3, cg = (u & 7) << 3;
      uint4 v = make_uint4(0u,0u,0u,0u);
      int m = m0 + row;
      if (m < M) v = *reinterpret_cast<const uint4*>(Asrc + (size_t)m*ldx + kc + cg);
      *reinterpret_cast<uint4*>(&As[row][cg]) = v;
    }
    // stage B: 64 rows x 64 bf16
#pragma unroll
    for (int i=0;i<2;i++){
      int u = tid + (i<<8);
      int row = u >> 3, cg = (u & 7) << 3;
      uint4 v = *reinterpret_cast<const uint4*>(Bb + (size_t)(n0+row)*ldb + k0 + cg);
      *reinterpret_cast<uint4*>(&Bs[row][cg]) = v;
    }
    __syncthreads();
#pragma unroll
    for (int kk=0;kk<4;kk++){
      int ks = kk*16;
      uint32_t afr[2][4], bfr[4][2];
#pragma unroll
      for (int h=0;h<2;h++){
        uint32_t ad = smem_u32(&As[mb + h*16 + a_row][ks + a_kof]);
        LDM4(afr[h][0], afr[h][1], afr[h][2], afr[h][3], ad);
      }
#pragma unroll
      for (int g=0;g<2;g++){
        uint32_t bd = smem_u32(&Bs[nb + g*16 + b_row][ks + b_kof]);
        uint32_t r0,r1,r2,r3;
        LDM4(r0,r1,r2,r3, bd);
        bfr[g*2+0][0]=r0; bfr[g*2+0][1]=r1;    // n-frag lo8: (b0 k0-7, b1 k8-15)
        bfr[g*2+1][0]=r2; bfr[g*2+1][1]=r3;    // n-frag hi8
      }
#pragma unroll
      for (int h=0;h<2;h++)
#pragma unroll
        for (int f=0;f<4;f++)
          MMA16816(acc[h][f], afr[h], bfr[f]);
    }
    __syncthreads();
  }

  // epilogue: c frag m16n8 -> rows mb+h*16+{r4, r4+8}, cols nb+f*8+c2
  int r4 = lane >> 2, c2 = (lane & 3) * 2;
#pragma unroll
  for (int h=0;h<2;h++){
#pragma unroll
    for (int f=0;f<4;f++){
#pragma unroll
      for (int half=0; half<2; half++){
        int m = m0 + mb + h*16 + r4 + half*8;
        if (m < M){
          int n = n0 + nb + f*8 + c2;
          float lo = acc[h][f][half*2+0];
          float hi = acc[h][f][half*2+1];
          if (bias){ lo += bias[n]; hi += bias[n+1]; }
          if (act){ lo = tanhf(lo); hi = tanhf(hi); }
          if (Cb) *reinterpret_cast<float2*>(&Cb[(size_t)m*ldc + n]) = make_float2(lo, hi);
          if (Cbb){
            __nv_bfloat162 bv; bv.x = __float2bfloat16(lo); bv.y = __float2bfloat16(hi);
            *reinterpret_cast<__nv_bfloat162*>(&Cbb[(size_t)m*ldc + n]) = bv;
          }
        }
      }
    }
  }
}

// ------------- NN GEMM: C = A(MxK) * B(KxN) (ctx only) -------------
__global__ void __launch_bounds__(256) k_gemm_nn(
    const float* __restrict__ A, int lda, long long sA,
    const float* __restrict__ B, int ldb, long long sB,
    float* __restrict__ C, int ldc, long long sC,
    int M, int N, int K)
{
  __shared__ float As[16][68];
  __shared__ float Bs[16][68];
  int z = blockIdx.z;
  const float* Ab = A + (size_t)z*sA;
  const float* Bb = B + (size_t)z*sB;
  float* Cb = C + (size_t)z*sC;
  int m0 = blockIdx.y*64, n0 = blockIdx.x*64;
  int tid = threadIdx.x;
  int tx = tid & 15, ty = tid >> 4;
  float acc[4][4];
#pragma unroll
  for (int i=0;i<4;i++)
#pragma unroll
    for (int j=0;j<4;j++) acc[i][j]=0.f;

  int r = tid >> 2, c4 = (tid & 3)*4;
  int kr = tid >> 4, nc4 = (tid & 15)*4;

  for (int k0=0;k0<K;k0+=16){
    float4 va = make_float4(0.f,0.f,0.f,0.f);
    int m = m0 + r;
    if (m < M) va = *reinterpret_cast<const float4*>(Ab + (size_t)m*lda + k0 + c4);
    As[c4+0][r]=va.x; As[c4+1][r]=va.y; As[c4+2][r]=va.z; As[c4+3][r]=va.w;
    float4 vb = *reinterpret_cast<const float4*>(Bb + (size_t)(k0+kr)*ldb + n0 + nc4);
    Bs[kr][nc4+0]=vb.x; Bs[kr][nc4+1]=vb.y; Bs[kr][nc4+2]=vb.z; Bs[kr][nc4+3]=vb.w;
    __syncthreads();
#pragma unroll
    for (int kk=0;kk<16;kk++){
      float4 a = *reinterpret_cast<const float4*>(&As[kk][ty*4]);
      float4 b = *reinterpret_cast<const float4*>(&Bs[kk][tx*4]);
      acc[0][0]+=a.x*b.x; acc[0][1]+=a.x*b.y; acc[0][2]+=a.x*b.z; acc[0][3]+=a.x*b.w;
      acc[1][0]+=a.y*b.x; acc[1][1]+=a.y*b.y; acc[1][2]+=a.y*b.z; acc[1][3]+=a.y*b.w;
      acc[2][0]+=a.z*b.x; acc[2][1]+=a.z*b.y; acc[2][2]+=a.z*b.z; acc[2][3]+=a.z*b.w;
      acc[3][0]+=a.w*b.x; acc[3][1]+=a.w*b.y; acc[3][2]+=a.w*b.z; acc[3][3]+=a.w*b.w;
    }
    __syncthreads();
  }
#pragma unroll
  for (int i=0;i<4;i++){
    int m = m0 + ty*4 + i;
    if (m < M){
#pragma unroll
      for (int j=0;j<4;j++) Cb[(size_t)m*ldc + (n0 + tx*4 + j)] = acc[i][j];
    }
  }
}

// ------------- persistent wavefront recurrence (R10, unchanged) -------------
__device__ __forceinline__ void gridbar(unsigned target){
  __threadfence();
  __syncthreads();
  if (threadIdx.x == 0){
    atomicAdd(&g_barc, 1u);
    while (*(volatile unsigned*)&g_barc < target) { __nanosleep(64); }
  }
  __syncthreads();
}

__device__ __forceinline__ void stage_q(const float* __restrict__ src, int kbase, float* buf){
  int tid = threadIdx.x;
#pragma unroll
  for (int i=0;i<2;i++){
    int idx = tid + (i<<9);
    int b = idx >> 6, c = idx & 63;
    ((float4*)buf)[idx] = __ldcg((const float4*)(src + (b<<10) + kbase) + c);
  }
}

__device__ __forceinline__ void dot_q(const float* __restrict__ W, int kbase,
    const float* __restrict__ buf, int ju, int lane, int B0, ull (&acc)[4][8])
{
#pragma unroll
  for (int m=0;m<2;m++){
    int kq = (lane<<2) + (m<<7);
    ulonglong2 wv[4];
#pragma unroll
    for (int r=0;r<4;r++)
      wv[r] = __ldcg((const ulonglong2*)(W + ((size_t)(ju + (r<<10)))*1024 + kbase + kq));
#pragma unroll
    for (int bb=0;bb<8;bb++){
      ulonglong2 hv = *(const ulonglong2*)(buf + ((B0+bb)<<8) + kq);
#pragma unroll
      for (int r=0;r<4;r++){
        FMA2(acc[r][bb], wv[r].x, hv.x);
        FMA2(acc[r][bb], wv[r].y, hv.y);
      }
    }
  }
}

__device__ __forceinline__ void zacc(ull (&acc)[4][8]){
#pragma unroll
  for (int r=0;r<4;r++)
#pragma unroll
    for (int bb=0;bb<8;bb++) acc[r][bb] = 0ull;
}

__device__ __forceinline__ float reduce32(ull (&acc)[4][8], int lane){
  float v[32];
#pragma unroll
  for (int r=0;r<4;r++)
#pragma unroll
    for (int bb=0;bb<8;bb++){
      ull x = acc[r][bb];
      v[r*8+bb] = __uint_as_float((unsigned)x) + __uint_as_float((unsigned)(x>>32));
    }
#pragma unroll
  for (int off=16; off>=1; off>>=1){
#pragma unroll
    for (int i=0;i<16;i++){
      if (i < off){
        float a = (lane & off) ? v[i+off] : v[i];
        float b = (lane & off) ? v[i]     : v[i+off];
        v[i] = a + __shfl_xor_sync(0xffffffffu, b, off);
      }
    }
  }
  return v[0];
}

__device__ __forceinline__ void lstm_epi(
    ull (&acc)[4][8], int lane, int ju, int B0, float bias,
    const float* x0p, float& c, float* hdst, float* hsdst, int t, bool active)
{
  int mybb = lane & 7;
  float g = reduce32(acc, lane) + bias;
  if (x0p) g += __ldcg(x0p);
  float gi = __shfl_sync(0xffffffffu, g, mybb);
  float gf = __shfl_sync(0xffffffffu, g, 8 + mybb);
  float gg = __shfl_sync(0xffffffffu, g, 16 + mybb);
  float go = __shfl_sync(0xffffffffu, g, 24 + mybb);
  if (active && lane < 8){
    float iv=sigm(gi), fv=sigm(gf), gv=tanhf(gg), ov=sigm(go);
    c = fv*c + iv*gv;
    float h = ov * tanhf(c);
    int b = B0 + lane;
    hdst[(b<<10) + ju] = h;
    if (hsdst) hsdst[((size_t)b*TSTEPS + t)*HSZ + ju] = h;
  }
}

__global__ void __launch_bounds__(512,1) k_recur(
    const float* __restrict__ Whh0, const float* __restrict__ bi0, const float* __restrict__ bh0,
    const float* __restrict__ Wih1, const float* __restrict__ Whh1,
    const float* __restrict__ bi1, const float* __restrict__ bh1,
    const float* __restrict__ Wih2, const float* __restrict__ Whh2,
    const float* __restrict__ bi2, const float* __restrict__ bh2)
{
  __shared__ __align__(16) float buf[2][BSZ*256];
  int tid = threadIdx.x, lane = tid & 31, wid = tid >> 5;
  int ju = blockIdx.x*8 + (wid >> 1);
  int B0 = (wid & 1) * 8;
  int myr = lane >> 3, mybb = lane & 7;

  float bias0, bias1, bias2;
  {
    int rr = (myr<<10) + ju;
    bias0 = bi0[rr] + bh0[rr];
    bias1 = bi1[rr] + bh1[rr];
    bias2 = bi2[rr] + bh2[rr];
  }

  float c0 = 0.f, c1 = 0.f, c2 = 0.f;
  ull acc[4][8];

  for (int p = 0; p < TSTEPS + 2; p++){
    int t0 = p, t1 = p - 1, t2 = p - 2;
    const float* S[5] = { g_h[0][(t0+1)&1], g_h[0][t1&1], g_h[1][(t1+1)&1],
                          g_h[1][t2&1],     g_h[2][(t2+1)&1] };
    const float* W[5] = { Whh0, Wih1, Whh1, Wih2, Whh2 };

    const float* x0p = (t0 < TSTEPS)
      ? &g_X0[((size_t)(t0*BSZ + B0 + mybb))*4096 + (myr<<10) + ju] : nullptr;

    stage_q(S[0], 0, buf[0]);
    __syncthreads();
    zacc(acc);
#pragma unroll
    for (int q = 0; q < 20; q++){
      if (q < 19) stage_q(S[(q+1)>>2], ((q+1)&3)<<8, buf[(q+1)&1]);
      dot_q(W[q>>2], (q&3)<<8, buf[q&1], ju, lane, B0, acc);
      if (q == 3){
        lstm_epi(acc, lane, ju, B0, bias0, x0p, c0, g_h[0][t0&1], nullptr, t0, t0 < TSTEPS);
        zacc(acc);
      } else if (q == 11){
        lstm_epi(acc, lane, ju, B0, bias1, nullptr, c1, g_h[1][t1&1], nullptr, t1,
                 (t1 >= 0) && (t1 < TSTEPS));
        zacc(acc);
      } else if (q == 19){
        lstm_epi(acc, lane, ju, B0, bias2, nullptr, c2, g_h[2][t2&1], g_hs, t2, t2 >= 0);
      }
      if (q < 19) __syncthreads();
    }
    gridbar((unsigned)(p+1) * NB);
  }
}

// ------------- softmax over S=512 -------------
__global__ void k_softmax(){
  int m = blockIdx.x;
  float* row = g_att + (size_t)m * SENC;
  int tid = threadIdx.x;
  __shared__ float sm[4];
  float v[4];
#pragma unroll
  for (int i=0;i<4;i++) v[i] = row[tid + 128*i];
  float mx = fmaxf(fmaxf(v[0],v[1]), fmaxf(v[2],v[3]));
#pragma unroll
  for (int o=16;o>0;o>>=1) mx = fmaxf(mx, __shfl_xor_sync(0xffffffffu, mx, o));
  if ((tid & 31) == 0) sm[tid>>5] = mx;
  __syncthreads();
  mx = fmaxf(fmaxf(sm[0],sm[1]), fmaxf(sm[2],sm[3]));
  float s = 0.f;
#pragma unroll
  for (int i=0;i<4;i++){ v[i] = expf(v[i]-mx); s += v[i]; }
#pragma unroll
  for (int o=16;o>0;o>>=1) s += __shfl_xor_sync(0xffffffffu, s, o);
  __syncthreads();
  if ((tid & 31) == 0) sm[tid>>5] = s;
  __syncthreads();
  s = sm[0]+sm[1]+sm[2]+sm[3];
  float inv = 1.f / s;
#pragma unroll
  for (int i=0;i<4;i++) row[tid + 128*i] = v[i]*inv;
}

// ------------- NLL over V=1024 -------------
__global__ void k_nll(){
  int m = blockIdx.x;
  const float* row = g_logits + (size_t)m * 1024;
  int tid = threadIdx.x;
  __shared__ float sm[8];
  float v[4];
#pragma unroll
  for (int i=0;i<4;i++) v[i] = row[tid + 256*i];
  float mx = fmaxf(fmaxf(v[0],v[1]), fmaxf(v[2],v[3]));
#pragma unroll
  for (int o=16;o>0;o>>=1) mx = fmaxf(mx, __shfl_xor_sync(0xffffffffu, mx, o));
  if ((tid & 31) == 0) sm[tid>>5] = mx;
  __syncthreads();
  mx = sm[0];
#pragma unroll
  for (int i=1;i<8;i++) mx = fmaxf(mx, sm[i]);
  float s = 0.f;
#pragma unroll
  for (int i=0;i<4;i++) s += expf(v[i]-mx);
#pragma unroll
  for (int o=16;o>0;o>>=1) s += __shfl_xor_sync(0xffffffffu, s, o);
  __syncthreads();
  if ((tid & 31) == 0) sm[tid>>5] = s;
  __syncthreads();
  if (tid == 0){
    float tot = 0.f;
#pragma unroll
    for (int i=0;i<8;i++) tot += sm[i];
    g_nll[m] = (logf(tot) + mx) - row[g_tgt[m]];
  }
}

__global__ void k_final(float* __restrict__ out){
  int tid = threadIdx.x;
  __shared__ float sm[8];
  float s = 0.f;
  for (int i=tid; i<MROWS; i+=256) s += g_nll[i];
#pragma unroll
  for (int o=16;o>0;o>>=1) s += __shfl_xor_sync(0xffffffffu, s, o);
  if ((tid & 31) == 0) sm[tid>>5] = s;
  __syncthreads();
  if (tid == 0){
    float tot = 0.f;
#pragma unroll
    for (int i=0;i<8;i++) tot += sm[i];
    out[0] = tot / (float)MROWS;
  }
}

// ------------- launcher -------------
extern "C" void kernel_launch(void* const* d_in, const int* in_sizes, int n_in,
                              void* d_out, int out_size)
{
  const int*   tokens = (const int*)  d_in[0];
  const float* enc    = (const float*)d_in[1];
  const float* emb    = (const float*)d_in[2];
  const float* Wih0   = (const float*)d_in[3];
  const float* Whh0   = (const float*)d_in[4];
  const float* bi0    = (const float*)d_in[5];
  const float* bh0    = (const float*)d_in[6];
  const float* Wih1   = (const float*)d_in[7];
  const float* Whh1   = (const float*)d_in[8];
  const float* bi1    = (const float*)d_in[9];
  const float* bh1    = (const float*)d_in[10];
  const float* Wih2   = (const float*)d_in[11];
  const float* Whh2   = (const float*)d_in[12];
  const float* bi2    = (const float*)d_in[13];
  const float* bh2    = (const float*)d_in[14];
  const float* W1     = (const float*)d_in[15];
  const float* b1     = (const float*)d_in[16];
  const float* W2     = (const float*)d_in[17];
  const float* b2     = (const float*)d_in[18];
  float* out = (float*)d_out;

  void *pX0,*pHS,*pCTX,*pATT,*pLOG,*pHSB,*pCTXB,*pHIDB,*pENCB,*pW1B,*pW2B;
  cudaGetSymbolAddress(&pX0,  g_X0);
  cudaGetSymbolAddress(&pHS,  g_hs);
  cudaGetSymbolAddress(&pCTX, g_ctx);
  cudaGetSymbolAddress(&pATT, g_att);
  cudaGetSymbolAddress(&pLOG, g_logits);
  cudaGetSymbolAddress(&pHSB, g_hsb);
  cudaGetSymbolAddress(&pCTXB,g_ctxb);
  cudaGetSymbolAddress(&pHIDB,g_hidb);
  cudaGetSymbolAddress(&pENCB,g_encb);
  cudaGetSymbolAddress(&pW1B, g_W1b);
  cudaGetSymbolAddress(&pW2B, g_W2b);
  float* X0 = (float*)pX0;

  k_init<<<384,256>>>(tokens);

  // bf16 operand converts (independent of the recurrence)
  k_cvt<<<(BSZ*SENC*HSZ+255)/256,256>>>(enc, (__nv_bfloat16*)pENCB, BSZ*SENC*HSZ);
  k_cvt<<<(HSZ*2048+255)/256,256>>>(W1, (__nv_bfloat16*)pW1B, HSZ*2048);
  k_cvt<<<(HSZ*HSZ+255)/256,256>>>(W2, (__nv_bfloat16*)pW2B, HSZ*HSZ);

  // X0 (fp32, feeds the recurrence)
  k_gemm_nt<<<dim3(32,33,1),256>>>(emb,ESZ,0, nullptr,ESZ,1<<30, 1,
                                   Wih0,1536,0, X0, 4096,0,
                                   MROWS,4096,ESZ, nullptr,0);

  k_recur<<<NB,512>>>(Whh0,bi0,bh0, Wih1,Whh1,bi1,bh1, Wih2,Whh2,bi2,bh2);

  k_cvt<<<((int)((size_t)MROWS*HSZ)+255)/256,256>>>((const float*)pHS, (__nv_bfloat16*)pHSB, MROWS*HSZ);

  // scores[b] = hs[b] @ enc[b]^T  (HMMA bf16)
  k_gemm_tc<<<dim3(8,3,16),256>>>((const __nv_bfloat16*)pHSB,1024,257LL*1024,
                                  nullptr,0,1<<30,
                                  (const __nv_bfloat16*)pENCB,1024,512LL*1024,
                                  (float*)pATT,512,257LL*512, nullptr,
                                  257,512,1024, nullptr,0);

  k_softmax<<<MROWS,128>>>();

  // ctx[b] = attn[b] @ enc[b]  (fp32)
  k_gemm_nn<<<dim3(16,5,16),256>>>((const float*)pATT,512,257LL*512,
                                   enc,1024,512LL*1024,
                                   (float*)pCTX,1024,257LL*1024, 257,1024,512);

  k_cvt<<<((int)((size_t)MROWS*HSZ)+255)/256,256>>>((const float*)pCTX, (__nv_bfloat16*)pCTXB, MROWS*HSZ);

  // hidden = tanh([hs|ctx] @ W1^T + b1) -> bf16 mirror only
  k_gemm_tc<<<dim3(16,33,1),256>>>((const __nv_bfloat16*)pHSB,1024,0,
                                   (const __nv_bfloat16*)pCTXB,1024,1024,
                                   (const __nv_bfloat16*)pW1B,2048,0,
                                   nullptr,1024,0, (__nv_bfloat16*)pHIDB,
                                   MROWS,1024,2048, b1,1);

  // logits = hidden @ W2^T + b2  (fp32 out)
  k_gemm_tc<<<dim3(16,33,1),256>>>((const __nv_bfloat16*)pHIDB,1024,0,
                                   nullptr,0,1<<30,
                                   (const __nv_bfloat16*)pW2B,1024,0,
                                   (float*)pLOG,1024,0, nullptr,
                                   MROWS,1024,1024, b2,0);

  k_nll<<<MROWS,256>>>();
  k_final<<<1,256>>>(out);
}

// round 15
// speedup vs baseline: 3.0213x; 1.2370x over previous
#include <cuda_runtime.h>
#include <cuda_bf16.h>
#include <cstdint>
#include <cstddef>

#define HSZ 1024
#define BSZ 16
#define TSTEPS 257
#define SENC 512
#define ESZ 512
#define MROWS (BSZ*TSTEPS)
#define NB 128
typedef unsigned long long ull;

// ------------- device scratch (statics; no allocations) -------------
__device__ float g_X0[(size_t)MROWS * 4096];      // [t*16+b][gate_row]
__device__ float g_ctx[(size_t)MROWS * HSZ];
__device__ float g_att[(size_t)MROWS * SENC];
__device__ float g_logits[(size_t)MROWS * HSZ];
__device__ float g_nll[MROWS];
__device__ int   g_tok[MROWS];
__device__ int   g_tgt[MROWS];
__device__ unsigned g_barc;
// bf16 state + operands
__device__ __nv_bfloat16 g_hb[3][2][BSZ*HSZ];     // ping-pong hidden (bf16)
__device__ __nv_bfloat16 g_Wb[5][(size_t)4096*1024]; // Whh0,Wih1,Whh1,Wih2,Whh2
__device__ __nv_bfloat16 g_hsb[(size_t)MROWS * HSZ];
__device__ __nv_bfloat16 g_ctxb[(size_t)MROWS * HSZ];
__device__ __nv_bfloat16 g_hidb[(size_t)MROWS * HSZ];
__device__ __nv_bfloat16 g_encb[(size_t)BSZ * SENC * HSZ];
__device__ __nv_bfloat16 g_W1b[(size_t)HSZ * 2048];
__device__ __nv_bfloat16 g_W2b[(size_t)HSZ * HSZ];

#define FMA2(a,x,y) asm("fma.rn.f32x2 %0, %1, %2, %0;" : "+l"(a) : "l"(x), "l"(y))
#define PACK2(o,f)  asm("mov.b64 %0, {%1, %1};" : "=l"(o) : "r"(__float_as_uint(f)))
__device__ __forceinline__ float sigm(float x){ return 1.f/(1.f+expf(-x)); }

__device__ __forceinline__ uint32_t smem_u32(const void* p){
  uint32_t a;
  asm("{ .reg .u64 t; cvta.to.shared.u64 t, %1; cvt.u32.u64 %0, t; }" : "=r"(a) : "l"(p));
  return a;
}

#define LDM4(r0,r1,r2,r3,ad) \
  asm volatile("ldmatrix.sync.aligned.m8n8.x4.shared.b16 {%0,%1,%2,%3}, [%4];" \
    : "=r"(r0),"=r"(r1),"=r"(r2),"=r"(r3) : "r"(ad))
#define LDM2(r0,r1,ad) \
  asm volatile("ldmatrix.sync.aligned.m8n8.x2.shared.b16 {%0,%1}, [%2];" \
    : "=r"(r0),"=r"(r1) : "r"(ad))
#define MMA16816(c,a,b) \
  asm volatile("mma.sync.aligned.m16n8k16.row.col.f32.bf16.bf16.f32 " \
    "{%0,%1,%2,%3}, {%4,%5,%6,%7}, {%8,%9}, {%0,%1,%2,%3};" \
    : "+f"(c[0]),"+f"(c[1]),"+f"(c[2]),"+f"(c[3]) \
    : "r"(a[0]),"r"(a[1]),"r"(a[2]),"r"(a[3]), "r"(b[0]),"r"(b[1]))

// ------------- init -------------
__global__ void k_init(const int* __restrict__ tokens){
  int i = blockIdx.x*blockDim.x + threadIdx.x;
  if (i == 0) g_barc = 0u;
  if (i < 3*2*BSZ*HSZ) ((__nv_bfloat16*)g_hb)[i] = __float2bfloat16(0.f);
  if (i < MROWS){
    int t = i / BSZ, b = i % BSZ;
    g_tok[i] = (t == 0) ? 1 : tokens[b*256 + (t-1)];
    int b2 = i / TSTEPS, t2 = i % TSTEPS;
    g_tgt[i] = (t2 < 256) ? tokens[b2*256 + t2] : 2;
  }
}

__global__ void k_cvt(const float* __restrict__ src, __nv_bfloat16* __restrict__ dst, int n){
  int i = blockIdx.x*blockDim.x + threadIdx.x;
  if (i < n) dst[i] = __float2bfloat16(src[i]);
}

// ------------- NT GEMM 128x128 fp32 (X0 only) -------------
__global__ void __launch_bounds__(256) k_gemm_nt(
    const float* __restrict__ A, int lda, long long sA,
    const float* __restrict__ A2, int lda2, int ksplit, int gather,
    const float* __restrict__ B, int ldb, long long sB,
    float* __restrict__ C, int ldc, long long sC,
    int M, int N, int K, const float* __restrict__ bias, int act)
{
  __shared__ __align__(16) float As[16][132];
  __shared__ __align__(16) float Bs[16][132];
  int z = blockIdx.z;
  const float* Ab = A + (size_t)z * sA;
  const float* Bb = B + (size_t)z * sB;
  float* Cb = C + (size_t)z * sC;
  int m0 = blockIdx.y*128, n0 = blockIdx.x*128;
  int tid = threadIdx.x;
  int tx = tid & 15, ty = tid >> 4;

  ull acc[8][4];
#pragma unroll
  for (int i=0;i<8;i++)
#pragma unroll
    for (int j=0;j<4;j++) acc[i][j] = 0ull;

  for (int k0 = 0; k0 < K; k0 += 16){
#pragma unroll
    for (int i=0;i<2;i++){
      int f = tid + (i<<8);
      int row = f >> 2, c4 = (f & 3) * 4;
      float4 va = make_float4(0.f,0.f,0.f,0.f);
      int m = m0 + row;
      if (m < M){
        int kg = k0 + c4;
        int arow = gather ? g_tok[m] : m;
        const float* src;
        if (A2 && kg >= ksplit) src = A2 + (size_t)arow*lda2 + (kg - ksplit);
        else                    src = Ab + (size_t)arow*lda + kg;
        va = *reinterpret_cast<const float4*>(src);
      }
      As[c4+0][row]=va.x; As[c4+1][row]=va.y; As[c4+2][row]=va.z; As[c4+3][row]=va.w;
      float4 vb = *reinterpret_cast<const float4*>(Bb + (size_t)(n0+row)*ldb + k0 + c4);
      Bs[c4+0][row]=vb.x; Bs[c4+1][row]=vb.y; Bs[c4+2][row]=vb.z; Bs[c4+3][row]=vb.w;
    }
    __syncthreads();
#pragma unroll
    for (int kk=0;kk<16;kk++){
      float4 a0 = *reinterpret_cast<const float4*>(&As[kk][ty*8]);
      float4 a1 = *reinterpret_cast<const float4*>(&As[kk][ty*8+4]);
      ulonglong2 b0 = *reinterpret_cast<const ulonglong2*>(&Bs[kk][tx*8]);
      ulonglong2 b1 = *reinterpret_cast<const ulonglong2*>(&Bs[kk][tx*8+4]);
      float af[8] = {a0.x,a0.y,a0.z,a0.w,a1.x,a1.y,a1.z,a1.w};
#pragma unroll
      for (int i=0;i<8;i++){
        ull aa; PACK2(aa, af[i]);
        FMA2(acc[i][0], aa, b0.x);
        FMA2(acc[i][1], aa, b0.y);
        FMA2(acc[i][2], aa, b1.x);
        FMA2(acc[i][3], aa, b1.y);
      }
    }
    __syncthreads();
  }
#pragma unroll
  for (int i=0;i<8;i++){
    int m = m0 + ty*8 + i;
    if (m < M){
#pragma unroll
      for (int j=0;j<4;j++){
        int n = n0 + tx*8 + j*2;
        ull v = acc[i][j];
        float lo = __uint_as_float((unsigned)v);
        float hi = __uint_as_float((unsigned)(v>>32));
        if (bias){ lo += bias[n]; hi += bias[n+1]; }
        if (act){ lo = tanhf(lo); hi = tanhf(hi); }
        *reinterpret_cast<float2*>(&Cb[(size_t)m*ldc + n]) = make_float2(lo, hi);
      }
    }
  }
}

// ------------- HMMA bf16 NT GEMM (tail; verified R13) -------------
__global__ void __launch_bounds__(256) k_gemm_tc(
    const __nv_bfloat16* __restrict__ A, int lda, long long sA,
    const __nv_bfloat16* __restrict__ A2, int lda2, int ksplit,
    const __nv_bfloat16* __restrict__ B, int ldb, long long sB,
    float* __restrict__ C, int ldc, long long sC,
    __nv_bfloat16* __restrict__ Cbf,
    int M, int N, int K, const float* __restrict__ bias, int act)
{
  __shared__ __align__(16) __nv_bfloat16 As[128][72];
  __shared__ __align__(16) __nv_bfloat16 Bs[64][72];
  int z = blockIdx.z;
  const __nv_bfloat16* Ab = A + (size_t)z * sA;
  const __nv_bfloat16* Bb = B + (size_t)z * sB;
  float* Cb = C ? C + (size_t)z * sC : nullptr;
  __nv_bfloat16* Cbb = Cbf ? Cbf + (size_t)z * sC : nullptr;
  int m0 = blockIdx.y*128, n0 = blockIdx.x*64;
  int tid = threadIdx.x, wid = tid >> 5, lane = tid & 31;
  int wm = wid >> 1, wn = wid & 1;
  int mb = wm*32, nb = wn*32;

  float acc[2][4][4];
#pragma unroll
  for (int h=0;h<2;h++)
#pragma unroll
    for (int f=0;f<4;f++)
#pragma unroll
      for (int e=0;e<4;e++) acc[h][f][e] = 0.f;

  int q = lane >> 3, l8 = lane & 7;
  int a_row = l8 + (q & 1)*8, a_kof = (q >> 1)*8;
  int b_row = l8 + (q >> 1)*8, b_kof = (q & 1)*8;

  for (int k0 = 0; k0 < K; k0 += 64){
    const __nv_bfloat16* Asrc; int kc, ldx;
    if (A2 && k0 >= ksplit){ Asrc = A2; kc = k0 - ksplit; ldx = lda2; }
    else                   { Asrc = Ab; kc = k0;          ldx = lda;  }
#pragma unroll
    for (int i=0;i<4;i++){
      int u = tid + (i<<8);
      int row = u >> 3, cg = (u & 7) << 3;
      uint4 v = make_uint4(0u,0u,0u,0u);
      int m = m0 + row;
      if (m < M) v = *reinterpret_cast<const uint4*>(Asrc + (size_t)m*ldx + kc + cg);
      *reinterpret_cast<uint4*>(&As[row][cg]) = v;
    }
#pragma unroll
    for (int i=0;i<2;i++){
      int u = tid + (i<<8);
      int row = u >> 3, cg = (u & 7) << 3;
      uint4 v = *reinterpret_cast<const uint4*>(Bb + (size_t)(n0+row)*ldb + k0 + cg);
      *reinterpret_cast<uint4*>(&Bs[row][cg]) = v;
    }
    __syncthreads();
#pragma unroll
    for (int kk=0;kk<4;kk++){
      int ks = kk*16;
      uint32_t afr[2][4], bfr[4][2];
#pragma unroll
      for (int h=0;h<2;h++){
        uint32_t ad = smem_u32(&As[mb + h*16 + a_row][ks + a_kof]);
        LDM4(afr[h][0], afr[h][1], afr[h][2], afr[h][3], ad);
      }
#pragma unroll
      for (int g=0;g<2;g++){
        uint32_t bd = smem_u32(&Bs[nb + g*16 + b_row][ks + b_kof]);
        uint32_t r0,r1,r2,r3;
        LDM4(r0,r1,r2,r3, bd);
        bfr[g*2+0][0]=r0; bfr[g*2+0][1]=r1;
        bfr[g*2+1][0]=r2; bfr[g*2+1][1]=r3;
      }
#pragma unroll
      for (int h=0;h<2;h++)
#pragma unroll
        for (int f=0;f<4;f++)
          MMA16816(acc[h][f], afr[h], bfr[f]);
    }
    __syncthreads();
  }

  int r4 = lane >> 2, c2 = (lane & 3) * 2;
#pragma unroll
  for (int h=0;h<2;h++){
#pragma unroll
    for (int f=0;f<4;f++){
#pragma unroll
      for (int half=0; half<2; half++){
        int m = m0 + mb + h*16 + r4 + half*8;
        if (m < M){
          int n = n0 + nb + f*8 + c2;
          float lo = acc[h][f][half*2+0];
          float hi = acc[h][f][half*2+1];
          if (bias){ lo += bias[n]; hi += bias[n+1]; }
          if (act){ lo = tanhf(lo); hi = tanhf(hi); }
          if (Cb) *reinterpret_cast<float2*>(&Cb[(size_t)m*ldc + n]) = make_float2(lo, hi);
          if (Cbb){
            __nv_bfloat162 bv; bv.x = __float2bfloat16(lo); bv.y = __float2bfloat16(hi);
            *reinterpret_cast<__nv_bfloat162*>(&Cbb[(size_t)m*ldc + n]) = bv;
          }
        }
      }
    }
  }
}

// ------------- NN GEMM fp32 (ctx only) -------------
__global__ void __launch_bounds__(256) k_gemm_nn(
    const float* __restrict__ A, int lda, long long sA,
    const float* __restrict__ B, int ldb, long long sB,
    float* __restrict__ C, int ldc, long long sC,
    int M, int N, int K)
{
  __shared__ float As[16][68];
  __shared__ float Bs[16][68];
  int z = blockIdx.z;
  const float* Ab = A + (size_t)z*sA;
  const float* Bb = B + (size_t)z*sB;
  float* Cb = C + (size_t)z*sC;
  int m0 = blockIdx.y*64, n0 = blockIdx.x*64;
  int tid = threadIdx.x;
  int tx = tid & 15, ty = tid >> 4;
  float acc[4][4];
#pragma unroll
  for (int i=0;i<4;i++)
#pragma unroll
    for (int j=0;j<4;j++) acc[i][j]=0.f;

  int r = tid >> 2, c4 = (tid & 3)*4;
  int kr = tid >> 4, nc4 = (tid & 15)*4;

  for (int k0=0;k0<K;k0+=16){
    float4 va = make_float4(0.f,0.f,0.f,0.f);
    int m = m0 + r;
    if (m < M) va = *reinterpret_cast<const float4*>(Ab + (size_t)m*lda + k0 + c4);
    As[c4+0][r]=va.x; As[c4+1][r]=va.y; As[c4+2][r]=va.z; As[c4+3][r]=va.w;
    float4 vb = *reinterpret_cast<const float4*>(Bb + (size_t)(k0+kr)*ldb + n0 + nc4);
    Bs[kr][nc4+0]=vb.x; Bs[kr][nc4+1]=vb.y; Bs[kr][nc4+2]=vb.z; Bs[kr][nc4+3]=vb.w;
    __syncthreads();
#pragma unroll
    for (int kk=0;kk<16;kk++){
      float4 a = *reinterpret_cast<const float4*>(&As[kk][ty*4]);
      float4 b = *reinterpret_cast<const float4*>(&Bs[kk][tx*4]);
      acc[0][0]+=a.x*b.x; acc[0][1]+=a.x*b.y; acc[0][2]+=a.x*b.z; acc[0][3]+=a.x*b.w;
      acc[1][0]+=a.y*b.x; acc[1][1]+=a.y*b.y; acc[1][2]+=a.y*b.z; acc[1][3]+=a.y*b.w;
      acc[2][0]+=a.z*b.x; acc[2][1]+=a.z*b.y; acc[2][2]+=a.z*b.z; acc[2][3]+=a.z*b.w;
      acc[3][0]+=a.w*b.x; acc[3][1]+=a.w*b.y; acc[3][2]+=a.w*b.z; acc[3][3]+=a.w*b.w;
    }
    __syncthreads();
  }
#pragma unroll
  for (int i=0;i<4;i++){
    int m = m0 + ty*4 + i;
    if (m < M){
#pragma unroll
      for (int j=0;j<4;j++) Cb[(size_t)m*ldc + (n0 + tx*4 + j)] = acc[i][j];
    }
  }
}

// ------------- HMMA persistent wavefront recurrence -------------
__device__ __forceinline__ void gridbar(unsigned target){
  __threadfence();
  __syncthreads();
  if (threadIdx.x == 0){
    atomicAdd(&g_barc, 1u);
    while (*(volatile unsigned*)&g_barc < target) { __nanosleep(64); }
  }
  __syncthreads();
}

__global__ void __launch_bounds__(256,1) k_recur(
    const float* __restrict__ bi0, const float* __restrict__ bh0,
    const float* __restrict__ bi1, const float* __restrict__ bh1,
    const float* __restrict__ bi2, const float* __restrict__ bh2)
{
  // eighth-slice tiles: h 16x128, W 32x128, stride 136 bf16 (272B, 16B mult)
  __shared__ __align__(16) __nv_bfloat16 Hq[2][16][136];
  __shared__ __align__(16) __nv_bfloat16 Wq[2][32][136];
  __shared__ float sgate[4][16][8];
  __shared__ float sbias[3][4][8];
  int tid = threadIdx.x, lane = tid & 31, wid = tid >> 5;
  int j0 = blockIdx.x*8;
  int r = wid & 3, khalf = wid >> 2;     // warp: gate r, K-half
  int q4 = lane >> 3, l8 = lane & 7;
  int a_row = l8 + (q4 & 1)*8, a_kof = (q4 >> 1)*8;
  int b_kof = ((lane >> 3) & 1)*8;       // lanes 0-15 meaningful for x2

  if (tid < 96){
    int l = tid >> 5, rr = (tid >> 3) & 3, jj = tid & 7;
    const float* bi = (l==0)?bi0:((l==1)?bi1:bi2);
    const float* bh = (l==0)?bh0:((l==1)?bh1:bh2);
    int row = (rr<<10) + j0 + jj;
    sbias[l][rr][jj] = bi[row] + bh[row];
  }
  float c0 = 0.f, c1 = 0.f, c2 = 0.f;    // cell state in epilogue threads (tid<128)
  __syncthreads();

  for (int p = 0; p < TSTEPS + 2; p++){
    int t0 = p, t1 = p - 1, t2 = p - 2;
    const __nv_bfloat16* S[5] = {
      g_hb[0][(t0+1)&1], g_hb[0][t1&1], g_hb[1][(t1+1)&1],
      g_hb[1][t2&1],     g_hb[2][(t2+1)&1] };

    // stage eighth 0
    {
      int row = tid >> 4, c8 = (tid & 15) << 3;
      *reinterpret_cast<uint4*>(&Hq[0][row][c8]) =
        __ldcg((const uint4*)(S[0] + (row<<10) + c8));
#pragma unroll
      for (int i=0;i<2;i++){
        int u = tid + (i<<8);
        int wrow = u >> 4, wc8 = (u & 15) << 3;
        int grow = ((wrow>>3)<<10) + j0 + (wrow&7);
        *reinterpret_cast<uint4*>(&Wq[0][wrow][wc8]) =
          *reinterpret_cast<const uint4*>(g_Wb[0] + (size_t)grow*1024 + wc8);
      }
    }
    __syncthreads();

    float acc[4] = {0.f, 0.f, 0.f, 0.f};
    for (int q = 0; q < 40; q++){
      int buf = q & 1;
      if (q < 39){
        int qn = q + 1, g = qn >> 3, kb = (qn & 7) << 7, nb = qn & 1;
        int row = tid >> 4, c8 = (tid & 15) << 3;
        *reinterpret_cast<uint4*>(&Hq[nb][row][c8]) =
          __ldcg((const uint4*)(S[g] + (row<<10) + kb + c8));
#pragma unroll
        for (int i=0;i<2;i++){
          int u = tid + (i<<8);
          int wrow = u >> 4, wc8 = (u & 15) << 3;
          int grow = ((wrow>>3)<<10) + j0 + (wrow&7);
          *reinterpret_cast<uint4*>(&Wq[nb][wrow][wc8]) =
            *reinterpret_cast<const uint4*>(g_Wb[g] + (size_t)grow*1024 + kb + wc8);
        }
      }
      // dot: 4 k-steps over this warp's K-half of the eighth
#pragma unroll
      for (int ks=0; ks<4; ks++){
        int kk = (khalf<<6) + (ks<<4);
        uint32_t af[4];
        LDM4(af[0],af[1],af[2],af[3], smem_u32(&Hq[buf][a_row][kk + a_kof]));
        uint32_t bfr[2];
        LDM2(bfr[0],bfr[1], smem_u32(&Wq[buf][(r<<3) + l8][kk + b_kof]));
        MMA16816(acc, af, bfr);
      }

      if (q == 7 || q == 23 || q == 39){
        __syncthreads();
        // partner-warp reduce into sgate: warps 4-7 write, warps 0-3 add
        if (khalf == 1){
          sgate[r][lane>>2][(lane&3)*2]       = acc[0];
          sgate[r][lane>>2][(lane&3)*2+1]     = acc[1];
          sgate[r][(lane>>2)+8][(lane&3)*2]   = acc[2];
          sgate[r][(lane>>2)+8][(lane&3)*2+1] = acc[3];
        }
        __syncthreads();
        if (khalf == 0){
          sgate[r][lane>>2][(lane&3)*2]       += acc[0];
          sgate[r][lane>>2][(lane&3)*2+1]     += acc[1];
          sgate[r][(lane>>2)+8][(lane&3)*2]   += acc[2];
          sgate[r][(lane>>2)+8][(lane&3)*2+1] += acc[3];
        }
        __syncthreads();
        int l = (q == 7) ? 0 : ((q == 23) ? 1 : 2);
        int t = (q == 7) ? t0 : ((q == 23) ? t1 : t2);
        if (tid < 128 && t >= 0 && t < TSTEPS){
          int b = tid >> 3, jj = tid & 7;
          float gi = sgate[0][b][jj] + sbias[l][0][jj];
          float gf = sgate[1][b][jj] + sbias[l][1][jj];
          float gg = sgate[2][b][jj] + sbias[l][2][jj];
          float go = sgate[3][b][jj] + sbias[l][3][jj];
          if (l == 0){
            const float* x0 = g_X0 + ((size_t)(t*BSZ + b))*4096 + j0 + jj;
            gi += __ldcg(x0);
            gf += __ldcg(x0 + 1024);
            gg += __ldcg(x0 + 2048);
            go += __ldcg(x0 + 3072);
          }
          float& c = (l==0) ? c0 : ((l==1) ? c1 : c2);
          float iv = sigm(gi), fv = sigm(gf), gv = tanhf(gg), ov = sigm(go);
          c = fv*c + iv*gv;
          float h = ov * tanhf(c);
          __nv_bfloat16 hb = __float2bfloat16(h);
          g_hb[l][t&1][(b<<10) + j0 + jj] = hb;
          if (l == 2) g_hsb[((size_t)b*TSTEPS + t)*HSZ + j0 + jj] = hb;
        }
        acc[0]=0.f; acc[1]=0.f; acc[2]=0.f; acc[3]=0.f;
        __syncthreads();
      } else {
        __syncthreads();
      }
    }
    gridbar((unsigned)(p+1) * NB);
  }
}

// ------------- softmax over S=512 -------------
__global__ void k_softmax(){
  int m = blockIdx.x;
  float* row = g_att + (size_t)m * SENC;
  int tid = threadIdx.x;
  __shared__ float sm[4];
  float v[4];
#pragma unroll
  for (int i=0;i<4;i++) v[i] = row[tid + 128*i];
  float mx = fmaxf(fmaxf(v[0],v[1]), fmaxf(v[2],v[3]));
#pragma unroll
  for (int o=16;o>0;o>>=1) mx = fmaxf(mx, __shfl_xor_sync(0xffffffffu, mx, o));
  if ((tid & 31) == 0) sm[tid>>5] = mx;
  __syncthreads();
  mx = fmaxf(fmaxf(sm[0],sm[1]), fmaxf(sm[2],sm[3]));
  float s = 0.f;
#pragma unroll
  for (int i=0;i<4;i++){ v[i] = expf(v[i]-mx); s += v[i]; }
#pragma unroll
  for (int o=16;o>0;o>>=1) s += __shfl_xor_sync(0xffffffffu, s, o);
  __syncthreads();
  if ((tid & 31) == 0) sm[tid>>5] = s;
  __syncthreads();
  s = sm[0]+sm[1]+sm[2]+sm[3];
  float inv = 1.f / s;
#pragma unroll
  for (int i=0;i<4;i++) row[tid + 128*i] = v[i]*inv;
}

// ------------- NLL over V=1024 -------------
__global__ void k_nll(){
  int m = blockIdx.x;
  const float* row = g_logits + (size_t)m * 1024;
  int tid = threadIdx.x;
  __shared__ float sm[8];
  float v[4];
#pragma unroll
  for (int i=0;i<4;i++) v[i] = row[tid + 256*i];
  float mx = fmaxf(fmaxf(v[0],v[1]), fmaxf(v[2],v[3]));
#pragma unroll
  for (int o=16;o>0;o>>=1) mx = fmaxf(mx, __shfl_xor_sync(0xffffffffu, mx, o));
  if ((tid & 31) == 0) sm[tid>>5] = mx;
  __syncthreads();
  mx = sm[0];
#pragma unroll
  for (int i=1;i<8;i++) mx = fmaxf(mx, sm[i]);
  float s = 0.f;
#pragma unroll
  for (int i=0;i<4;i++) s += expf(v[i]-mx);
#pragma unroll
  for (int o=16;o>0;o>>=1) s += __shfl_xor_sync(0xffffffffu, s, o);
  __syncthreads();
  if ((tid & 31) == 0) sm[tid>>5] = s;
  __syncthreads();
  if (tid == 0){
    float tot = 0.f;
#pragma unroll
    for (int i=0;i<8;i++) tot += sm[i];
    g_nll[m] = (logf(tot) + mx) - row[g_tgt[m]];
  }
}

__global__ void k_final(float* __restrict__ out){
  int tid = threadIdx.x;
  __shared__ float sm[8];
  float s = 0.f;
  for (int i=tid; i<MROWS; i+=256) s += g_nll[i];
#pragma unroll
  for (int o=16;o>0;o>>=1) s += __shfl_xor_sync(0xffffffffu, s, o);
  if ((tid & 31) == 0) sm[tid>>5] = s;
  __syncthreads();
  if (tid == 0){
    float tot = 0.f;
#pragma unroll
    for (int i=0;i<8;i++) tot += sm[i];
    out[0] = tot / (float)MROWS;
  }
}

// ------------- launcher -------------
extern "C" void kernel_launch(void* const* d_in, const int* in_sizes, int n_in,
                              void* d_out, int out_size)
{
  const int*   tokens = (const int*)  d_in[0];
  const float* enc    = (const float*)d_in[1];
  const float* emb    = (const float*)d_in[2];
  const float* Wih0   = (const float*)d_in[3];
  const float* Whh0   = (const float*)d_in[4];
  const float* bi0    = (const float*)d_in[5];
  const float* bh0    = (const float*)d_in[6];
  const float* Wih1   = (const float*)d_in[7];
  const float* Whh1   = (const float*)d_in[8];
  const float* bi1    = (const float*)d_in[9];
  const float* bh1    = (const float*)d_in[10];
  const float* Wih2   = (const float*)d_in[11];
  const float* Whh2   = (const float*)d_in[12];
  const float* bi2    = (const float*)d_in[13];
  const float* bh2    = (const float*)d_in[14];
  const float* W1     = (const float*)d_in[15];
  const float* b1     = (const float*)d_in[16];
  const float* W2     = (const float*)d_in[17];
  const float* b2     = (const float*)d_in[18];
  float* out = (float*)d_out;

  void *pX0,*pCTX,*pATT,*pLOG,*pHSB,*pCTXB,*pHIDB,*pENCB,*pW1B,*pW2B,*pWB;
  cudaGetSymbolAddress(&pX0,  g_X0);
  cudaGetSymbolAddress(&pCTX, g_ctx);
  cudaGetSymbolAddress(&pATT, g_att);
  cudaGetSymbolAddress(&pLOG, g_logits);
  cudaGetSymbolAddress(&pHSB, g_hsb);
  cudaGetSymbolAddress(&pCTXB,g_ctxb);
  cudaGetSymbolAddress(&pHIDB,g_hidb);
  cudaGetSymbolAddress(&pENCB,g_encb);
  cudaGetSymbolAddress(&pW1B, g_W1b);
  cudaGetSymbolAddress(&pW2B, g_W2b);
  cudaGetSymbolAddress(&pWB,  g_Wb);
  float* X0 = (float*)pX0;
  __nv_bfloat16* Wb = (__nv_bfloat16*)pWB;
  const int WSZ = 4096*1024;

  k_init<<<384,256>>>(tokens);

  // bf16 converts: recurrence weights {Whh0, Wih1, Whh1, Wih2, Whh2} + tail operands
  k_cvt<<<(WSZ+255)/256,256>>>(Whh0, Wb + 0LL*WSZ, WSZ);
  k_cvt<<<(WSZ+255)/256,256>>>(Wih1, Wb + 1LL*WSZ, WSZ);
  k_cvt<<<(WSZ+255)/256,256>>>(Whh1, Wb + 2LL*WSZ, WSZ);
  k_cvt<<<(WSZ+255)/256,256>>>(Wih2, Wb + 3LL*WSZ, WSZ);
  k_cvt<<<(WSZ+255)/256,256>>>(Whh2, Wb + 4LL*WSZ, WSZ);
  k_cvt<<<(BSZ*SENC*HSZ+255)/256,256>>>(enc, (__nv_bfloat16*)pENCB, BSZ*SENC*HSZ);
  k_cvt<<<(HSZ*2048+255)/256,256>>>(W1, (__nv_bfloat16*)pW1B, HSZ*2048);
  k_cvt<<<(HSZ*HSZ+255)/256,256>>>(W2, (__nv_bfloat16*)pW2B, HSZ*HSZ);

  // X0 (fp32, feeds the recurrence epilogue)
  k_gemm_nt<<<dim3(32,33,1),256>>>(emb,ESZ,0, nullptr,ESZ,1<<30, 1,
                                   Wih0,1536,0, X0, 4096,0,
                                   MROWS,4096,ESZ, nullptr,0);

  k_recur<<<NB,256>>>(bi0,bh0, bi1,bh1, bi2,bh2);

  // scores[b] = hs[b] @ enc[b]^T  (HMMA bf16)
  k_gemm_tc<<<dim3(8,3,16),256>>>((const __nv_bfloat16*)pHSB,1024,257LL*1024,
                                  nullptr,0,1<<30,
                                  (const __nv_bfloat16*)pENCB,1024,512LL*1024,
                                  (float*)pATT,512,257LL*512, nullptr,
                                  257,512,1024, nullptr,0);

  k_softmax<<<MROWS,128>>>();

  // ctx[b] = attn[b] @ enc[b]  (fp32)
  k_gemm_nn<<<dim3(16,5,16),256>>>((const float*)pATT,512,257LL*512,
                                   enc,1024,512LL*1024,
                                   (float*)pCTX,1024,257LL*1024, 257,1024,512);

  k_cvt<<<((int)((size_t)MROWS*HSZ)+255)/256,256>>>((const float*)pCTX, (__nv_bfloat16*)pCTXB, MROWS*HSZ);

  // hidden = tanh([hs|ctx] @ W1^T + b1) -> bf16 mirror
  k_gemm_tc<<<dim3(16,33,1),256>>>((const __nv_bfloat16*)pHSB,1024,0,
                                   (const __nv_bfloat16*)pCTXB,1024,1024,
                                   (const __nv_bfloat16*)pW1B,2048,0,
                                   nullptr,1024,0, (__nv_bfloat16*)pHIDB,
                                   MROWS,1024,2048, b1,1);

  // logits = hidden @ W2^T + b2  (fp32 out)
  k_gemm_tc<<<dim3(16,33,1),256>>>((const __nv_bfloat16*)pHIDB,1024,0,
                                   nullptr,0,1<<30,
                                   (const __nv_bfloat16*)pW2B,1024,0,
                                   (float*)pLOG,1024,0, nullptr,
                                   MROWS,1024,1024, b2,0);

  k_nll<<<MROWS,256>>>();
  k_final<<<1,256>>>(out);
}

// round 16
// speedup vs baseline: 3.1742x; 1.0506x over previous
#include <cuda_runtime.h>
#include <cuda_bf16.h>
#include <cstdint>
#include <cstddef>

#define HSZ 1024
#define BSZ 16
#define TSTEPS 257
#define SENC 512
#define ESZ 512
#define MROWS (BSZ*TSTEPS)
#define NB 128
typedef unsigned long long ull;

// ------------- device scratch (statics; no allocations) -------------
__device__ float g_X0[(size_t)MROWS * 4096];      // [t*16+b][gate_row]
__device__ float g_ctx[(size_t)MROWS * HSZ];
__device__ float g_att[(size_t)MROWS * SENC];
__device__ float g_logits[(size_t)MROWS * HSZ];
__device__ float g_nll[MROWS];
__device__ int   g_tok[MROWS];
__device__ int   g_tgt[MROWS];
__device__ unsigned g_barc;
// bf16 state + operands
__device__ __nv_bfloat16 g_hb[3][2][BSZ*HSZ];     // ping-pong hidden (bf16)
__device__ __nv_bfloat16 g_Wb[5][(size_t)4096*1024]; // Whh0,Wih1,Whh1,Wih2,Whh2
__device__ __nv_bfloat16 g_hsb[(size_t)MROWS * HSZ];
__device__ __nv_bfloat16 g_ctxb[(size_t)MROWS * HSZ];
__device__ __nv_bfloat16 g_hidb[(size_t)MROWS * HSZ];
__device__ __nv_bfloat16 g_encb[(size_t)BSZ * SENC * HSZ];
__device__ __nv_bfloat16 g_W1b[(size_t)HSZ * 2048];
__device__ __nv_bfloat16 g_W2b[(size_t)HSZ * HSZ];
__device__ __nv_bfloat16 g_embb[(size_t)1024 * ESZ];
__device__ __nv_bfloat16 g_Wih0b[(size_t)4096 * 1536];

__device__ __forceinline__ float sigm(float x){ return 1.f/(1.f+expf(-x)); }

__device__ __forceinline__ uint32_t smem_u32(const void* p){
  uint32_t a;
  asm("{ .reg .u64 t; cvta.to.shared.u64 t, %1; cvt.u32.u64 %0, t; }" : "=r"(a) : "l"(p));
  return a;
}

#define LDM4(r0,r1,r2,r3,ad) \
  asm volatile("ldmatrix.sync.aligned.m8n8.x4.shared.b16 {%0,%1,%2,%3}, [%4];" \
    : "=r"(r0),"=r"(r1),"=r"(r2),"=r"(r3) : "r"(ad))
#define LDM2(r0,r1,ad) \
  asm volatile("ldmatrix.sync.aligned.m8n8.x2.shared.b16 {%0,%1}, [%2];" \
    : "=r"(r0),"=r"(r1) : "r"(ad))
#define MMA16816(c,a,b) \
  asm volatile("mma.sync.aligned.m16n8k16.row.col.f32.bf16.bf16.f32 " \
    "{%0,%1,%2,%3}, {%4,%5,%6,%7}, {%8,%9}, {%0,%1,%2,%3};" \
    : "+f"(c[0]),"+f"(c[1]),"+f"(c[2]),"+f"(c[3]) \
    : "r"(a[0]),"r"(a[1]),"r"(a[2]),"r"(a[3]), "r"(b[0]),"r"(b[1]))

// ------------- init -------------
__global__ void k_init(const int* __restrict__ tokens){
  int i = blockIdx.x*blockDim.x + threadIdx.x;
  if (i == 0) g_barc = 0u;
  if (i < 3*2*BSZ*HSZ) ((__nv_bfloat16*)g_hb)[i] = __float2bfloat16(0.f);
  if (i < MROWS){
    int t = i / BSZ, b = i % BSZ;
    g_tok[i] = (t == 0) ? 1 : tokens[b*256 + (t-1)];
    int b2 = i / TSTEPS, t2 = i % TSTEPS;
    g_tgt[i] = (t2 < 256) ? tokens[b2*256 + t2] : 2;
  }
}

// vectorized fp32 -> bf16 (n multiple of 4)
__global__ void k_cvt(const float* __restrict__ src, __nv_bfloat16* __restrict__ dst, int n){
  int i = (blockIdx.x*blockDim.x + threadIdx.x) * 4;
  if (i < n){
    float4 v = *reinterpret_cast<const float4*>(src + i);
    *reinterpret_cast<__nv_bfloat162*>(dst + i)     = __floats2bfloat162_rn(v.x, v.y);
    *reinterpret_cast<__nv_bfloat162*>(dst + i + 2) = __floats2bfloat162_rn(v.z, v.w);
  }
}

// ------------- HMMA bf16 NT GEMM (verified R13; + gather flag) -------------
__global__ void __launch_bounds__(256) k_gemm_tc(
    const __nv_bfloat16* __restrict__ A, int lda, long long sA,
    const __nv_bfloat16* __restrict__ A2, int lda2, int ksplit,
    const __nv_bfloat16* __restrict__ B, int ldb, long long sB,
    float* __restrict__ C, int ldc, long long sC,
    __nv_bfloat16* __restrict__ Cbf,
    int M, int N, int K, const float* __restrict__ bias, int act, int gather)
{
  __shared__ __align__(16) __nv_bfloat16 As[128][72];
  __shared__ __align__(16) __nv_bfloat16 Bs[64][72];
  int z = blockIdx.z;
  const __nv_bfloat16* Ab = A + (size_t)z * sA;
  const __nv_bfloat16* Bb = B + (size_t)z * sB;
  float* Cb = C ? C + (size_t)z * sC : nullptr;
  __nv_bfloat16* Cbb = Cbf ? Cbf + (size_t)z * sC : nullptr;
  int m0 = blockIdx.y*128, n0 = blockIdx.x*64;
  int tid = threadIdx.x, wid = tid >> 5, lane = tid & 31;
  int wm = wid >> 1, wn = wid & 1;
  int mb = wm*32, nb = wn*32;

  float acc[2][4][4];
#pragma unroll
  for (int h=0;h<2;h++)
#pragma unroll
    for (int f=0;f<4;f++)
#pragma unroll
      for (int e=0;e<4;e++) acc[h][f][e] = 0.f;

  int q = lane >> 3, l8 = lane & 7;
  int a_row = l8 + (q & 1)*8, a_kof = (q >> 1)*8;
  int b_row = l8 + (q >> 1)*8, b_kof = (q & 1)*8;

  for (int k0 = 0; k0 < K; k0 += 64){
    const __nv_bfloat16* Asrc; int kc, ldx;
    if (A2 && k0 >= ksplit){ Asrc = A2; kc = k0 - ksplit; ldx = lda2; }
    else                   { Asrc = Ab; kc = k0;          ldx = lda;  }
#pragma unroll
    for (int i=0;i<4;i++){
      int u = tid + (i<<8);
      int row = u >> 3, cg = (u & 7) << 3;
      uint4 v = make_uint4(0u,0u,0u,0u);
      int m = m0 + row;
      if (m < M){
        int arow = gather ? g_tok[m] : m;
        v = *reinterpret_cast<const uint4*>(Asrc + (size_t)arow*ldx + kc + cg);
      }
      *reinterpret_cast<uint4*>(&As[row][cg]) = v;
    }
#pragma unroll
    for (int i=0;i<2;i++){
      int u = tid + (i<<8);
      int row = u >> 3, cg = (u & 7) << 3;
      uint4 v = *reinterpret_cast<const uint4*>(Bb + (size_t)(n0+row)*ldb + k0 + cg);
      *reinterpret_cast<uint4*>(&Bs[row][cg]) = v;
    }
    __syncthreads();
#pragma unroll
    for (int kk=0;kk<4;kk++){
      int ks = kk*16;
      uint32_t afr[2][4], bfr[4][2];
#pragma unroll
      for (int h=0;h<2;h++){
        uint32_t ad = smem_u32(&As[mb + h*16 + a_row][ks + a_kof]);
        LDM4(afr[h][0], afr[h][1], afr[h][2], afr[h][3], ad);
      }
#pragma unroll
      for (int g=0;g<2;g++){
        uint32_t bd = smem_u32(&Bs[nb + g*16 + b_row][ks + b_kof]);
        uint32_t r0,r1,r2,r3;
        LDM4(r0,r1,r2,r3, bd);
        bfr[g*2+0][0]=r0; bfr[g*2+0][1]=r1;
        bfr[g*2+1][0]=r2; bfr[g*2+1][1]=r3;
      }
#pragma unroll
      for (int h=0;h<2;h++)
#pragma unroll
        for (int f=0;f<4;f++)
          MMA16816(acc[h][f], afr[h], bfr[f]);
    }
    __syncthreads();
  }

  int r4 = lane >> 2, c2 = (lane & 3) * 2;
#pragma unroll
  for (int h=0;h<2;h++){
#pragma unroll
    for (int f=0;f<4;f++){
#pragma unroll
      for (int half=0; half<2; half++){
        int m = m0 + mb + h*16 + r4 + half*8;
        if (m < M){
          int n = n0 + nb + f*8 + c2;
          float lo = acc[h][f][half*2+0];
          float hi = acc[h][f][half*2+1];
          if (bias){ lo += bias[n]; hi += bias[n+1]; }
          if (act){ lo = tanhf(lo); hi = tanhf(hi); }
          if (Cb) *reinterpret_cast<float2*>(&Cb[(size_t)m*ldc + n]) = make_float2(lo, hi);
          if (Cbb){
            __nv_bfloat162 bv; bv.x = __float2bfloat16(lo); bv.y = __float2bfloat16(hi);
            *reinterpret_cast<__nv_bfloat162*>(&Cbb[(size_t)m*ldc + n]) = bv;
          }
        }
      }
    }
  }
}

// ------------- NN GEMM fp32 (ctx only) -------------
__global__ void __launch_bounds__(256) k_gemm_nn(
    const float* __restrict__ A, int lda, long long sA,
    const float* __restrict__ B, int ldb, long long sB,
    float* __restrict__ C, int ldc, long long sC,
    int M, int N, int K)
{
  __shared__ float As[16][68];
  __shared__ float Bs[16][68];
  int z = blockIdx.z;
  const float* Ab = A + (size_t)z*sA;
  const float* Bb = B + (size_t)z*sB;
  float* Cb = C + (size_t)z*sC;
  int m0 = blockIdx.y*64, n0 = blockIdx.x*64;
  int tid = threadIdx.x;
  int tx = tid & 15, ty = tid >> 4;
  float acc[4][4];
#pragma unroll
  for (int i=0;i<4;i++)
#pragma unroll
    for (int j=0;j<4;j++) acc[i][j]=0.f;

  int r = tid >> 2, c4 = (tid & 3)*4;
  int kr = tid >> 4, nc4 = (tid & 15)*4;

  for (int k0=0;k0<K;k0+=16){
    float4 va = make_float4(0.f,0.f,0.f,0.f);
    int m = m0 + r;
    if (m < M) va = *reinterpret_cast<const float4*>(Ab + (size_t)m*lda + k0 + c4);
    As[c4+0][r]=va.x; As[c4+1][r]=va.y; As[c4+2][r]=va.z; As[c4+3][r]=va.w;
    float4 vb = *reinterpret_cast<const float4*>(Bb + (size_t)(k0+kr)*ldb + n0 + nc4);
    Bs[kr][nc4+0]=vb.x; Bs[kr][nc4+1]=vb.y; Bs[kr][nc4+2]=vb.z; Bs[kr][nc4+3]=vb.w;
    __syncthreads();
#pragma unroll
    for (int kk=0;kk<16;kk++){
      float4 a = *reinterpret_cast<const float4*>(&As[kk][ty*4]);
      float4 b = *reinterpret_cast<const float4*>(&Bs[kk][tx*4]);
      acc[0][0]+=a.x*b.x; acc[0][1]+=a.x*b.y; acc[0][2]+=a.x*b.z; acc[0][3]+=a.x*b.w;
      acc[1][0]+=a.y*b.x; acc[1][1]+=a.y*b.y; acc[1][2]+=a.y*b.z; acc[1][3]+=a.y*b.w;
      acc[2][0]+=a.z*b.x; acc[2][1]+=a.z*b.y; acc[2][2]+=a.z*b.z; acc[2][3]+=a.z*b.w;
      acc[3][0]+=a.w*b.x; acc[3][1]+=a.w*b.y; acc[3][2]+=a.w*b.z; acc[3][3]+=a.w*b.w;
    }
    __syncthreads();
  }
#pragma unroll
  for (int i=0;i<4;i++){
    int m = m0 + ty*4 + i;
    if (m < M){
#pragma unroll
      for (int j=0;j<4;j++) Cb[(size_t)m*ldc + (n0 + tx*4 + j)] = acc[i][j];
    }
  }
}

// ------------- HMMA persistent wavefront recurrence (ring-3 prefetch) -------------
__device__ __forceinline__ void gridbar(unsigned target){
  __threadfence();
  __syncthreads();
  if (threadIdx.x == 0){
    atomicAdd(&g_barc, 1u);
    while (*(volatile unsigned*)&g_barc < target) { __nanosleep(64); }
  }
  __syncthreads();
}

__device__ __forceinline__ void stage_slice(int slice, int bufi, int tid, int j0,
    const __nv_bfloat16* const* S,
    __nv_bfloat16 (*Hq)[16][136], __nv_bfloat16 (*Wq)[32][136])
{
  int g = slice >> 3, kb = (slice & 7) << 7;
  int row = tid >> 4, c8 = (tid & 15) << 3;
  *reinterpret_cast<uint4*>(&Hq[bufi][row][c8]) =
    __ldcg((const uint4*)(S[g] + (row<<10) + kb + c8));
#pragma unroll
  for (int i=0;i<2;i++){
    int u = tid + (i<<8);
    int wrow = u >> 4, wc8 = (u & 15) << 3;
    int grow = ((wrow>>3)<<10) + j0 + (wrow&7);
    *reinterpret_cast<uint4*>(&Wq[bufi][wrow][wc8]) =
      *reinterpret_cast<const uint4*>(g_Wb[g] + (size_t)grow*1024 + kb + wc8);
  }
}

__global__ void __launch_bounds__(256,1) k_recur(
    const float* __restrict__ bi0, const float* __restrict__ bh0,
    const float* __restrict__ bi1, const float* __restrict__ bh1,
    const float* __restrict__ bi2, const float* __restrict__ bh2)
{
  __shared__ __align__(16) __nv_bfloat16 Hq[3][16][136];
  __shared__ __align__(16) __nv_bfloat16 Wq[3][32][136];
  __shared__ float sgate[4][16][8];
  __shared__ float sbias[3][4][8];
  int tid = threadIdx.x, lane = tid & 31, wid = tid >> 5;
  int j0 = blockIdx.x*8;
  int r = wid & 3, khalf = wid >> 2;
  int q4 = lane >> 3, l8 = lane & 7;
  int a_row = l8 + (q4 & 1)*8, a_kof = (q4 >> 1)*8;
  int b_kof = ((lane >> 3) & 1)*8;

  if (tid < 96){
    int l = tid >> 5, rr = (tid >> 3) & 3, jj = tid & 7;
    const float* bi = (l==0)?bi0:((l==1)?bi1:bi2);
    const float* bh = (l==0)?bh0:((l==1)?bh1:bh2);
    int row = (rr<<10) + j0 + jj;
    sbias[l][rr][jj] = bi[row] + bh[row];
  }
  float c0 = 0.f, c1 = 0.f, c2 = 0.f;
  __syncthreads();

  for (int p = 0; p < TSTEPS + 2; p++){
    int t0 = p, t1 = p - 1, t2 = p - 2;
    const __nv_bfloat16* S[5] = {
      g_hb[0][(t0+1)&1], g_hb[0][t1&1], g_hb[1][(t1+1)&1],
      g_hb[1][t2&1],     g_hb[2][(t2+1)&1] };

    stage_slice(0, 0, tid, j0, S, Hq, Wq);
    stage_slice(1, 1, tid, j0, S, Hq, Wq);
    __syncthreads();

    float acc[4] = {0.f, 0.f, 0.f, 0.f};
    int bufi = 0;
    for (int q = 0; q < 40; q++){
      if (q + 2 <= 39){
        int nb = bufi + 2; if (nb >= 3) nb -= 3;
        stage_slice(q + 2, nb, tid, j0, S, Hq, Wq);
      }
#pragma unroll
      for (int ks=0; ks<4; ks++){
        int kk = (khalf<<6) + (ks<<4);
        uint32_t af[4];
        LDM4(af[0],af[1],af[2],af[3], smem_u32(&Hq[bufi][a_row][kk + a_kof]));
        uint32_t bfr[2];
        LDM2(bfr[0],bfr[1], smem_u32(&Wq[bufi][(r<<3) + l8][kk + b_kof]));
        MMA16816(acc, af, bfr);
      }

      if (q == 7 || q == 23 || q == 39){
        __syncthreads();
        if (khalf == 1){
          sgate[r][lane>>2][(lane&3)*2]       = acc[0];
          sgate[r][lane>>2][(lane&3)*2+1]     = acc[1];
          sgate[r][(lane>>2)+8][(lane&3)*2]   = acc[2];
          sgate[r][(lane>>2)+8][(lane&3)*2+1] = acc[3];
        }
        __syncthreads();
        if (khalf == 0){
          sgate[r][lane>>2][(lane&3)*2]       += acc[0];
          sgate[r][lane>>2][(lane&3)*2+1]     += acc[1];
          sgate[r][(lane>>2)+8][(lane&3)*2]   += acc[2];
          sgate[r][(lane>>2)+8][(lane&3)*2+1] += acc[3];
        }
        __syncthreads();
        int l = (q == 7) ? 0 : ((q == 23) ? 1 : 2);
        int t = (q == 7) ? t0 : ((q == 23) ? t1 : t2);
        if (tid < 128 && t >= 0 && t < TSTEPS){
          int b = tid >> 3, jj = tid & 7;
          float gi = sgate[0][b][jj] + sbias[l][0][jj];
          float gf = sgate[1][b][jj] + sbias[l][1][jj];
          float gg = sgate[2][b][jj] + sbias[l][2][jj];
          float go = sgate[3][b][jj] + sbias[l][3][jj];
          if (l == 0){
            const float* x0 = g_X0 + ((size_t)(t*BSZ + b))*4096 + j0 + jj;
            gi += __ldcg(x0);
            gf += __ldcg(x0 + 1024);
            gg += __ldcg(x0 + 2048);
            go += __ldcg(x0 + 3072);
          }
          float& c = (l==0) ? c0 : ((l==1) ? c1 : c2);
          float iv = sigm(gi), fv = sigm(gf), gv = tanhf(gg), ov = sigm(go);
          c = fv*c + iv*gv;
          float h = ov * tanhf(c);
          __nv_bfloat16 hb = __float2bfloat16(h);
          g_hb[l][t&1][(b<<10) + j0 + jj] = hb;
          if (l == 2) g_hsb[((size_t)b*TSTEPS + t)*HSZ + j0 + jj] = hb;
        }
        acc[0]=0.f; acc[1]=0.f; acc[2]=0.f; acc[3]=0.f;
        __syncthreads();
      } else {
        __syncthreads();
      }
      if (++bufi >= 3) bufi = 0;
    }
    gridbar((unsigned)(p+1) * NB);
  }
}

// ------------- softmax over S=512 -------------
__global__ void k_softmax(){
  int m = blockIdx.x;
  float* row = g_att + (size_t)m * SENC;
  int tid = threadIdx.x;
  __shared__ float sm[4];
  float v[4];
#pragma unroll
  for (int i=0;i<4;i++) v[i] = row[tid + 128*i];
  float mx = fmaxf(fmaxf(v[0],v[1]), fmaxf(v[2],v[3]));
#pragma unroll
  for (int o=16;o>0;o>>=1) mx = fmaxf(mx, __shfl_xor_sync(0xffffffffu, mx, o));
  if ((tid & 31) == 0) sm[tid>>5] = mx;
  __syncthreads();
  mx = fmaxf(fmaxf(sm[0],sm[1]), fmaxf(sm[2],sm[3]));
  float s = 0.f;
#pragma unroll
  for (int i=0;i<4;i++){ v[i] = expf(v[i]-mx); s += v[i]; }
#pragma unroll
  for (int o=16;o>0;o>>=1) s += __shfl_xor_sync(0xffffffffu, s, o);
  __syncthreads();
  if ((tid & 31) == 0) sm[tid>>5] = s;
  __syncthreads();
  s = sm[0]+sm[1]+sm[2]+sm[3];
  float inv = 1.f / s;
#pragma unroll
  for (int i=0;i<4;i++) row[tid + 128*i] = v[i]*inv;
}

// ------------- NLL over V=1024 -------------
__global__ void k_nll(){
  int m = blockIdx.x;
  const float* row = g_logits + (size_t)m * 1024;
  int tid = threadIdx.x;
  __shared__ float sm[8];
  float v[4];
#pragma unroll
  for (int i=0;i<4;i++) v[i] = row[tid + 256*i];
  float mx = fmaxf(fmaxf(v[0],v[1]), fmaxf(v[2],v[3]));
#pragma unroll
  for (int o=16;o>0;o>>=1) mx = fmaxf(mx, __shfl_xor_sync(0xffffffffu, mx, o));
  if ((tid & 31) == 0) sm[tid>>5] = mx;
  __syncthreads();
  mx = sm[0];
#pragma unroll
  for (int i=1;i<8;i++) mx = fmaxf(mx, sm[i]);
  float s = 0.f;
#pragma unroll
  for (int i=0;i<4;i++) s += expf(v[i]-mx);
#pragma unroll
  for (int o=16;o>0;o>>=1) s += __shfl_xor_sync(0xffffffffu, s, o);
  __syncthreads();
  if ((tid & 31) == 0) sm[tid>>5] = s;
  __syncthreads();
  if (tid == 0){
    float tot = 0.f;
#pragma unroll
    for (int i=0;i<8;i++) tot += sm[i];
    g_nll[m] = (logf(tot) + mx) - row[g_tgt[m]];
  }
}

__global__ void k_final(float* __restrict__ out){
  int tid = threadIdx.x;
  __shared__ float sm[8];
  float s = 0.f;
  for (int i=tid; i<MROWS; i+=256) s += g_nll[i];
#pragma unroll
  for (int o=16;o>0;o>>=1) s += __shfl_xor_sync(0xffffffffu, s, o);
  if ((tid & 31) == 0) sm[tid>>5] = s;
  __syncthreads();
  if (tid == 0){
    float tot = 0.f;
#pragma unroll
    for (int i=0;i<8;i++) tot += sm[i];
    out[0] = tot / (float)MROWS;
  }
}

// ------------- launcher -------------
extern "C" void kernel_launch(void* const* d_in, const int* in_sizes, int n_in,
                              void* d_out, int out_size)
{
  const int*   tokens = (const int*)  d_in[0];
  const float* enc    = (const float*)d_in[1];
  const float* emb    = (const float*)d_in[2];
  const float* Wih0   = (const float*)d_in[3];
  const float* Whh0   = (const float*)d_in[4];
  const float* bi0    = (const float*)d_in[5];
  const float* bh0    = (const float*)d_in[6];
  const float* Wih1   = (const float*)d_in[7];
  const float* Whh1   = (const float*)d_in[8];
  const float* bi1    = (const float*)d_in[9];
  const float* bh1    = (const float*)d_in[10];
  const float* Wih2   = (const float*)d_in[11];
  const float* Whh2   = (const float*)d_in[12];
  const float* bi2    = (const float*)d_in[13];
  const float* bh2    = (const float*)d_in[14];
  const float* W1     = (const float*)d_in[15];
  const float* b1     = (const float*)d_in[16];
  const float* W2     = (const float*)d_in[17];
  const float* b2     = (const float*)d_in[18];
  float* out = (float*)d_out;

  void *pX0,*pCTX,*pATT,*pLOG,*pHSB,*pCTXB,*pHIDB,*pENCB,*pW1B,*pW2B,*pWB,*pEMB,*pWIH0B;
  cudaGetSymbolAddress(&pX0,  g_X0);
  cudaGetSymbolAddress(&pCTX, g_ctx);
  cudaGetSymbolAddress(&pATT, g_att);
  cudaGetSymbolAddress(&pLOG, g_logits);
  cudaGetSymbolAddress(&pHSB, g_hsb);
  cudaGetSymbolAddress(&pCTXB,g_ctxb);
  cudaGetSymbolAddress(&pHIDB,g_hidb);
  cudaGetSymbolAddress(&pENCB,g_encb);
  cudaGetSymbolAddress(&pW1B, g_W1b);
  cudaGetSymbolAddress(&pW2B, g_W2b);
  cudaGetSymbolAddress(&pWB,  g_Wb);
  cudaGetSymbolAddress(&pEMB, g_embb);
  cudaGetSymbolAddress(&pWIH0B, g_Wih0b);
  float* X0 = (float*)pX0;
  __nv_bfloat16* Wb = (__nv_bfloat16*)pWB;
  const int WSZ = 4096*1024;
  #define CVT(src,dst,n) k_cvt<<<((n)/4+255)/256,256>>>(src,(__nv_bfloat16*)(dst),n)

  k_init<<<384,256>>>(tokens);

  CVT(Whh0, Wb + 0LL*WSZ, WSZ);
  CVT(Wih1, Wb + 1LL*WSZ, WSZ);
  CVT(Whh1, Wb + 2LL*WSZ, WSZ);
  CVT(Wih2, Wb + 3LL*WSZ, WSZ);
  CVT(Whh2, Wb + 4LL*WSZ, WSZ);
  CVT(enc,  pENCB, BSZ*SENC*HSZ);
  CVT(W1,   pW1B,  HSZ*2048);
  CVT(W2,   pW2B,  HSZ*HSZ);
  CVT(emb,  pEMB,  1024*ESZ);
  CVT(Wih0, pWIH0B, 4096*1536);

  // X0 = gather(emb) @ Wih0[:, :512]^T  (HMMA, gather; fp32 out)
  k_gemm_tc<<<dim3(64,33,1),256>>>((const __nv_bfloat16*)pEMB,ESZ,0,
                                   nullptr,0,1<<30,
                                   (const __nv_bfloat16*)pWIH0B,1536,0,
                                   X0,4096,0, nullptr,
                                   MROWS,4096,ESZ, nullptr,0, 1);

  k_recur<<<NB,256>>>(bi0,bh0, bi1,bh1, bi2,bh2);

  // scores[b] = hs[b] @ enc[b]^T  (HMMA)
  k_gemm_tc<<<dim3(8,3,16),256>>>((const __nv_bfloat16*)pHSB,1024,257LL*1024,
                                  nullptr,0,1<<30,
                                  (const __nv_bfloat16*)pENCB,1024,512LL*1024,
                                  (float*)pATT,512,257LL*512, nullptr,
                                  257,512,1024, nullptr,0, 0);

  k_softmax<<<MROWS,128>>>();

  // ctx[b] = attn[b] @ enc[b]  (fp32)
  k_gemm_nn<<<dim3(16,5,16),256>>>((const float*)pATT,512,257LL*512,
                                   enc,1024,512LL*1024,
                                   (float*)pCTX,1024,257LL*1024, 257,1024,512);

  CVT((const float*)pCTX, pCTXB, MROWS*HSZ);

  // hidden = tanh([hs|ctx] @ W1^T + b1) -> bf16 mirror
  k_gemm_tc<<<dim3(16,33,1),256>>>((const __nv_bfloat16*)pHSB,1024,0,
                                   (const __nv_bfloat16*)pCTXB,1024,1024,
                                   (const __nv_bfloat16*)pW1B,2048,0,
                                   nullptr,1024,0, (__nv_bfloat16*)pHIDB,
                                   MROWS,1024,2048, b1,1, 0);

  // logits = hidden @ W2^T + b2  (fp32 out)
  k_gemm_tc<<<dim3(16,33,1),256>>>((const __nv_bfloat16*)pHIDB,1024,0,
                                   nullptr,0,1<<30,
                                   (const __nv_bfloat16*)pW2B,1024,0,
                                   (float*)pLOG,1024,0, nullptr,
                                   MROWS,1024,1024, b2,0, 0);

  k_nll<<<MROWS,256>>>();
  k_final<<<1,256>>>(out);
}